// round 4
// baseline (speedup 1.0000x reference)
#include <cuda_runtime.h>
#include <math.h>

// ---------------------------------------------------------------------------
// Problem dims
// ---------------------------------------------------------------------------
#define B_ 64
#define T_ 256
#define I_ 512
#define S_ 256
#define D_ 1024
#define H_ 1024
#define R_ 1280          // D_ + S_

// Scan kernel config
#define GBLK 128         // persistent blocks; 1 block/SM, all co-resident
#define TPB  256
#define JPB  8           // D_/GBLK h-columns per block
#define SPB  2           // S_/GBLK z-columns per block

// Shared memory layout (floats)
#define N_WHH (JPB * 3 * D_)          // 24576
#define N_WIH (JPB * 3 * S_)          // 6144
#define N_WMV (SPB * 2 * (I_ + D_))   // 6144
#define N_STG 8192                    // 128 k-rows x 64 batch staging tile
#define OFF_WIH (N_WHH)
#define OFF_WMV (OFF_WIH + N_WIH)
#define OFF_STG (OFF_WMV + N_WMV)
#define OFF_B   (OFF_STG + N_STG)
#define SCAN_SMEM_FLOATS (OFF_B + 64)
#define SCAN_SMEM_BYTES  (SCAN_SMEM_FLOATS * 4)   // 180,736 B < 227 KB

// ---------------------------------------------------------------------------
// Device-global scratch (no runtime allocation allowed)
// ---------------------------------------------------------------------------
__device__ __align__(256) float g_h[2][D_ * B_];     // [k][b], ping-pong
__device__ __align__(256) float g_z[2][S_ * B_];     // [s][b], ping-pong
__device__ __align__(256) float g_xT[T_ * I_ * B_];  // [t][i][b]
__device__ __align__(256) float g_rssm[(size_t)B_ * T_ * R_]; // [b][t][1280]
__device__ __align__(256) float g_a0[(size_t)B_ * T_ * H_];
__device__ __align__(256) float g_a1[(size_t)B_ * T_ * H_];
__device__ __align__(256) float g_dist[(size_t)B_ * T_ * I_];

__device__ unsigned g_bar_count;
__device__ volatile unsigned g_bar_sense;

// ---------------------------------------------------------------------------
// Software grid barrier (sense-reversal). All GBLK blocks are co-resident.
// ---------------------------------------------------------------------------
__device__ __forceinline__ void grid_sync() {
    __syncthreads();
    if (threadIdx.x == 0) {
        __threadfence();
        unsigned sense = g_bar_sense;
        unsigned prev = atomicAdd(&g_bar_count, 1u);
        if (prev == GBLK - 1) {
            g_bar_count = 0;
            __threadfence();
            g_bar_sense = sense + 1;
        } else {
            while (g_bar_sense == sense) { __nanosleep(64); }
        }
        __threadfence();
    }
    __syncthreads();
}

// Stage 8192 contiguous floats (128 k-rows x 64 b) into smem, coalesced.
__device__ __forceinline__ void stage8192(const float* __restrict__ src,
                                          float* __restrict__ dst) {
    const float4* s4 = (const float4*)src;
    float4* d4 = (float4*)dst;
    const int t = threadIdx.x;
#pragma unroll
    for (int i = 0; i < 8; i++) d4[t + i * TPB] = s4[t + i * TPB];
}

// ---------------------------------------------------------------------------
// Init: zero recurrent state ping-pong buffers
// ---------------------------------------------------------------------------
__global__ void init_state_kernel() {
    const int stride = gridDim.x * blockDim.x;
    float* h = &g_h[0][0];
    float* z = &g_z[0][0];
    for (int i = blockIdx.x * blockDim.x + threadIdx.x; i < 2 * D_ * B_; i += stride)
        h[i] = 0.f;
    for (int i = blockIdx.x * blockDim.x + threadIdx.x; i < 2 * S_ * B_; i += stride)
        z[i] = 0.f;
}

// ---------------------------------------------------------------------------
// Transpose x[b][t][i] -> g_xT[t][i][b]
// ---------------------------------------------------------------------------
__global__ void transpose_x_kernel(const float* __restrict__ x) {
    __shared__ float tile[64][65];
    const int t = blockIdx.x;
    const int c0 = blockIdx.y * 64;
    for (int l = threadIdx.x; l < 4096; l += TPB) {
        int b = l >> 6, c = l & 63;
        tile[b][c] = x[((size_t)b * T_ + t) * I_ + c0 + c];
    }
    __syncthreads();
    for (int l = threadIdx.x; l < 4096; l += TPB) {
        int c = l >> 6, b = l & 63;
        g_xT[((size_t)t * I_ + c0 + c) * B_ + b] = tile[b][c];
    }
}

// ---------------------------------------------------------------------------
// Persistent scan kernel: 256 GRU + posterior steps with 2 grid syncs/step
// ---------------------------------------------------------------------------
__global__ void __launch_bounds__(TPB, 1) scan_kernel(
    const float* __restrict__ W_ih, const float* __restrict__ W_hh,
    const float* __restrict__ b_ih, const float* __restrict__ b_hh,
    const float* __restrict__ Wm,   const float* __restrict__ bm,
    const float* __restrict__ Wv,   const float* __restrict__ bv,
    const float* __restrict__ noise)
{
    extern __shared__ float sm[];
    float* s_whh = sm;
    float* s_wih = sm + OFF_WIH;
    float* s_wmv = sm + OFF_WMV;
    float* s_stg = sm + OFF_STG;
    float* s_bih = sm + OFF_B;
    float* s_bhh = sm + OFF_B + 24;
    float* s_bmv = sm + OFF_B + 48;

    const int tid = threadIdx.x;
    const int bid = blockIdx.x;
    const int j0g = bid * JPB;   // first global h-column owned by this block
    const int s0g = bid * SPB;   // first global z-column

    // ---- load weight slices into smem (once; amortized over 256 steps) ----
    for (int row = 0; row < JPB * 3; ++row) {
        int jl = row / 3, g = row % 3;
        const float4* src = (const float4*)(W_hh + (size_t)(g * D_ + j0g + jl) * D_);
        float4* dst = (float4*)(s_whh + row * D_);
        dst[tid] = src[tid];                       // 256 float4 per row
    }
    for (int row = 0; row < JPB * 3; ++row) {
        int jl = row / 3, g = row % 3;
        const float4* src = (const float4*)(W_ih + (size_t)(g * D_ + j0g + jl) * S_);
        float4* dst = (float4*)(s_wih + row * S_);
        if (tid < 64) dst[tid] = src[tid];         // 64 float4 per row
    }
    for (int row = 0; row < SPB * 2; ++row) {
        int sl = row >> 1, mv = row & 1;
        const float* W = mv ? Wv : Wm;
        const float4* src = (const float4*)(W + (size_t)(s0g + sl) * (I_ + D_));
        float4* dst = (float4*)(s_wmv + row * (I_ + D_));
        for (int v = tid; v < 384; v += TPB) dst[v] = src[v];
    }
    if (tid < 24) {  // row = jl*3+g
        int jl = tid / 3, g = tid % 3;
        s_bih[tid] = b_ih[g * D_ + j0g + jl];
        s_bhh[tid] = b_hh[g * D_ + j0g + jl];
    }
    if (tid < 2) { s_bmv[tid * 2 + 0] = bm[s0g + tid]; s_bmv[tid * 2 + 1] = bv[s0g + tid]; }
    __syncthreads();

    const int grp = tid >> 6;       // 0..3
    const int b   = tid & 63;
    const int jl0 = grp * 2, jl1 = grp * 2 + 1;

    for (int t = 0; t < T_; ++t) {
        const int p = t & 1, pn = p ^ 1;
        const float* hprev = g_h[p];
        const float* zprev = g_z[p];

        // ================= Phase A: GRU cell =================
        float a_r0 = s_bih[jl0 * 3 + 0] + s_bhh[jl0 * 3 + 0];
        float a_z0 = s_bih[jl0 * 3 + 1] + s_bhh[jl0 * 3 + 1];
        float a_gin0 = s_bih[jl0 * 3 + 2];
        float a_ghn0 = s_bhh[jl0 * 3 + 2];
        float a_r1 = s_bih[jl1 * 3 + 0] + s_bhh[jl1 * 3 + 0];
        float a_z1 = s_bih[jl1 * 3 + 1] + s_bhh[jl1 * 3 + 1];
        float a_gin1 = s_bih[jl1 * 3 + 2];
        float a_ghn1 = s_bhh[jl1 * 3 + 2];

        // gi = z_prev @ W_ih.T   (K = 256, 2 chunks)
        for (int c = 0; c < 2; ++c) {
            __syncthreads();
            stage8192(zprev + c * N_STG, s_stg);
            __syncthreads();
            const float4* wr0 = (const float4*)(s_wih + (jl0 * 3 + 0) * S_ + c * 128);
            const float4* wz0 = (const float4*)(s_wih + (jl0 * 3 + 1) * S_ + c * 128);
            const float4* wn0 = (const float4*)(s_wih + (jl0 * 3 + 2) * S_ + c * 128);
            const float4* wr1 = (const float4*)(s_wih + (jl1 * 3 + 0) * S_ + c * 128);
            const float4* wz1 = (const float4*)(s_wih + (jl1 * 3 + 1) * S_ + c * 128);
            const float4* wn1 = (const float4*)(s_wih + (jl1 * 3 + 2) * S_ + c * 128);
#pragma unroll 8
            for (int k4 = 0; k4 < 32; ++k4) {
                float h0 = s_stg[(k4 * 4 + 0) * 64 + b];
                float h1 = s_stg[(k4 * 4 + 1) * 64 + b];
                float h2 = s_stg[(k4 * 4 + 2) * 64 + b];
                float h3 = s_stg[(k4 * 4 + 3) * 64 + b];
                float4 w;
                w = wr0[k4]; a_r0   += w.x*h0 + w.y*h1 + w.z*h2 + w.w*h3;
                w = wz0[k4]; a_z0   += w.x*h0 + w.y*h1 + w.z*h2 + w.w*h3;
                w = wn0[k4]; a_gin0 += w.x*h0 + w.y*h1 + w.z*h2 + w.w*h3;
                w = wr1[k4]; a_r1   += w.x*h0 + w.y*h1 + w.z*h2 + w.w*h3;
                w = wz1[k4]; a_z1   += w.x*h0 + w.y*h1 + w.z*h2 + w.w*h3;
                w = wn1[k4]; a_gin1 += w.x*h0 + w.y*h1 + w.z*h2 + w.w*h3;
            }
        }
        // gh = h_prev @ W_hh.T   (K = 1024, 8 chunks)
        for (int c = 0; c < 8; ++c) {
            __syncthreads();
            stage8192(hprev + c * N_STG, s_stg);
            __syncthreads();
            const float4* wr0 = (const float4*)(s_whh + (jl0 * 3 + 0) * D_ + c * 128);
            const float4* wz0 = (const float4*)(s_whh + (jl0 * 3 + 1) * D_ + c * 128);
            const float4* wn0 = (const float4*)(s_whh + (jl0 * 3 + 2) * D_ + c * 128);
            const float4* wr1 = (const float4*)(s_whh + (jl1 * 3 + 0) * D_ + c * 128);
            const float4* wz1 = (const float4*)(s_whh + (jl1 * 3 + 1) * D_ + c * 128);
            const float4* wn1 = (const float4*)(s_whh + (jl1 * 3 + 2) * D_ + c * 128);
#pragma unroll 8
            for (int k4 = 0; k4 < 32; ++k4) {
                float h0 = s_stg[(k4 * 4 + 0) * 64 + b];
                float h1 = s_stg[(k4 * 4 + 1) * 64 + b];
                float h2 = s_stg[(k4 * 4 + 2) * 64 + b];
                float h3 = s_stg[(k4 * 4 + 3) * 64 + b];
                float4 w;
                w = wr0[k4]; a_r0   += w.x*h0 + w.y*h1 + w.z*h2 + w.w*h3;
                w = wz0[k4]; a_z0   += w.x*h0 + w.y*h1 + w.z*h2 + w.w*h3;
                w = wn0[k4]; a_ghn0 += w.x*h0 + w.y*h1 + w.z*h2 + w.w*h3;
                w = wr1[k4]; a_r1   += w.x*h0 + w.y*h1 + w.z*h2 + w.w*h3;
                w = wz1[k4]; a_z1   += w.x*h0 + w.y*h1 + w.z*h2 + w.w*h3;
                w = wn1[k4]; a_ghn1 += w.x*h0 + w.y*h1 + w.z*h2 + w.w*h3;
            }
        }
        // finalize h_new
        {
            float hp0 = hprev[(j0g + jl0) * 64 + b];
            float hp1 = hprev[(j0g + jl1) * 64 + b];
            float r0 = 1.f / (1.f + expf(-a_r0));
            float zz0 = 1.f / (1.f + expf(-a_z0));
            float n0 = tanhf(a_gin0 + r0 * a_ghn0);
            float hn0 = (1.f - zz0) * n0 + zz0 * hp0;
            float r1 = 1.f / (1.f + expf(-a_r1));
            float zz1 = 1.f / (1.f + expf(-a_z1));
            float n1 = tanhf(a_gin1 + r1 * a_ghn1);
            float hn1 = (1.f - zz1) * n1 + zz1 * hp1;
            g_h[pn][(j0g + jl0) * 64 + b] = hn0;
            g_h[pn][(j0g + jl1) * 64 + b] = hn1;
            g_rssm[((size_t)b * T_ + t) * R_ + j0g + jl0] = hn0;
            g_rssm[((size_t)b * T_ + t) * R_ + j0g + jl1] = hn1;
        }

        grid_sync();   // all h_new visible

        // ================= Phase B: posterior =================
        const int sl = tid >> 6;  // valid for tid < 128
        float am = 0.f, av = 0.f;
        if (tid < 128) { am = s_bmv[sl * 2 + 0]; av = s_bmv[sl * 2 + 1]; }
        const float* hnew = g_h[pn];

        // x part (k = 0..511, 4 chunks)
        for (int c = 0; c < 4; ++c) {
            __syncthreads();
            stage8192(g_xT + ((size_t)t * I_ + c * 128) * 64, s_stg);
            __syncthreads();
            if (tid < 128) {
                const float4* wm4 = (const float4*)(s_wmv + (sl * 2 + 0) * 1536 + c * 128);
                const float4* wv4 = (const float4*)(s_wmv + (sl * 2 + 1) * 1536 + c * 128);
#pragma unroll 8
                for (int k4 = 0; k4 < 32; ++k4) {
                    float x0 = s_stg[(k4 * 4 + 0) * 64 + b];
                    float x1 = s_stg[(k4 * 4 + 1) * 64 + b];
                    float x2 = s_stg[(k4 * 4 + 2) * 64 + b];
                    float x3 = s_stg[(k4 * 4 + 3) * 64 + b];
                    float4 w;
                    w = wm4[k4]; am += w.x*x0 + w.y*x1 + w.z*x2 + w.w*x3;
                    w = wv4[k4]; av += w.x*x0 + w.y*x1 + w.z*x2 + w.w*x3;
                }
            }
        }
        // h part (k = 512..1535, 8 chunks)
        for (int c = 0; c < 8; ++c) {
            __syncthreads();
            stage8192(hnew + c * N_STG, s_stg);
            __syncthreads();
            if (tid < 128) {
                const float4* wm4 = (const float4*)(s_wmv + (sl * 2 + 0) * 1536 + 512 + c * 128);
                const float4* wv4 = (const float4*)(s_wmv + (sl * 2 + 1) * 1536 + 512 + c * 128);
#pragma unroll 8
                for (int k4 = 0; k4 < 32; ++k4) {
                    float x0 = s_stg[(k4 * 4 + 0) * 64 + b];
                    float x1 = s_stg[(k4 * 4 + 1) * 64 + b];
                    float x2 = s_stg[(k4 * 4 + 2) * 64 + b];
                    float x3 = s_stg[(k4 * 4 + 3) * 64 + b];
                    float4 w;
                    w = wm4[k4]; am += w.x*x0 + w.y*x1 + w.z*x2 + w.w*x3;
                    w = wv4[k4]; av += w.x*x0 + w.y*x1 + w.z*x2 + w.w*x3;
                }
            }
        }
        if (tid < 128) {
            int sg = s0g + sl;
            float nz = noise[((size_t)t * B_ + b) * S_ + sg];
            float zval = nz * expf(0.5f * av) + am;
            g_z[pn][sg * 64 + b] = zval;
            g_rssm[((size_t)b * T_ + t) * R_ + D_ + sg] = zval;
        }

        grid_sync();   // all z_new visible before next step's gi
    }
}

// ---------------------------------------------------------------------------
// Decoder SGEMM: C[M,N] = act(A[M,K] @ W[N,K]^T + bias), row-major, NT form
// ---------------------------------------------------------------------------
#define GM 128
#define GN 128
#define GK 16

__global__ void __launch_bounds__(256, 2) gemm_bias_act_kernel(
    const float* __restrict__ A, const float* __restrict__ W,
    const float* __restrict__ bias, float* __restrict__ C,
    int M, int N, int K, int act)
{
    __shared__ float As[GK][GM + 4];
    __shared__ float Ws[GK][GN + 4];
    const int tid = threadIdx.x;
    const int bm = blockIdx.y * GM;
    const int bn = blockIdx.x * GN;
    const int tx = tid & 15, ty = tid >> 4;

    float acc[8][8];
#pragma unroll
    for (int i = 0; i < 8; ++i)
#pragma unroll
        for (int j = 0; j < 8; ++j) acc[i][j] = 0.f;

    for (int kb = 0; kb < K; kb += GK) {
#pragma unroll
        for (int i = 0; i < 2; ++i) {
            int q = tid + i * 256;
            int row = q >> 2, part = q & 3;
            float4 v = *(const float4*)(A + (size_t)(bm + row) * K + kb + part * 4);
            As[part * 4 + 0][row] = v.x; As[part * 4 + 1][row] = v.y;
            As[part * 4 + 2][row] = v.z; As[part * 4 + 3][row] = v.w;
            float4 u = *(const float4*)(W + (size_t)(bn + row) * K + kb + part * 4);
            Ws[part * 4 + 0][row] = u.x; Ws[part * 4 + 1][row] = u.y;
            Ws[part * 4 + 2][row] = u.z; Ws[part * 4 + 3][row] = u.w;
        }
        __syncthreads();
#pragma unroll
        for (int k = 0; k < GK; ++k) {
            float ra[8], rw[8];
#pragma unroll
            for (int i = 0; i < 8; ++i) ra[i] = As[k][ty * 8 + i];
#pragma unroll
            for (int j = 0; j < 8; ++j) rw[j] = Ws[k][tx * 8 + j];
#pragma unroll
            for (int i = 0; i < 8; ++i)
#pragma unroll
                for (int j = 0; j < 8; ++j) acc[i][j] += ra[i] * rw[j];
        }
        __syncthreads();
    }

    float bb[8];
#pragma unroll
    for (int j = 0; j < 8; ++j) bb[j] = bias[bn + tx * 8 + j];
#pragma unroll
    for (int i = 0; i < 8; ++i) {
        float r[8];
#pragma unroll
        for (int j = 0; j < 8; ++j) {
            float v = acc[i][j] + bb[j];
            r[j] = act ? (v > 0.f ? v : expm1f(v)) : v;
        }
        float4* dst = (float4*)(C + (size_t)(bm + ty * 8 + i) * N + bn + tx * 8);
        dst[0] = make_float4(r[0], r[1], r[2], r[3]);
        dst[1] = make_float4(r[4], r[5], r[6], r[7]);
    }
}

// ---------------------------------------------------------------------------
// Epilogue: build (x_delta_hat, x_hat) into d_out
// ---------------------------------------------------------------------------
__global__ void epilogue_kernel(const float* __restrict__ x, float* __restrict__ out) {
    size_t idx = (size_t)blockIdx.x * blockDim.x + threadIdx.x;
    const size_t total = (size_t)B_ * T_ * I_;
    if (idx >= total) return;
    int i = (int)(idx & (I_ - 1));
    size_t bt = idx >> 9;
    int t = (int)(bt & (T_ - 1));
    int b = (int)(bt >> 8);

    // x_hat part (offset after x_delta_hat = 64*255*512)
    float xh;
    if (t == 0) xh = x[idx];
    else        xh = x[idx - I_] + g_dist[idx - I_];
    out[(size_t)B_ * (T_ - 1) * I_ + idx] = xh;

    // x_delta_hat part
    if (t < T_ - 1)
        out[((size_t)b * (T_ - 1) + t) * I_ + i] = g_dist[idx];
}

// ---------------------------------------------------------------------------
// kernel_launch
// ---------------------------------------------------------------------------
extern "C" void kernel_launch(void* const* d_in, const int* in_sizes, int n_in,
                              void* d_out, int out_size) {
    const float* x     = (const float*)d_in[0];
    const float* noise = (const float*)d_in[1];
    const float* W_ih  = (const float*)d_in[2];
    const float* W_hh  = (const float*)d_in[3];
    const float* b_ih  = (const float*)d_in[4];
    const float* b_hh  = (const float*)d_in[5];
    const float* Wm    = (const float*)d_in[6];
    const float* bm    = (const float*)d_in[7];
    const float* Wv    = (const float*)d_in[8];
    const float* bv    = (const float*)d_in[9];
    const float* dW0   = (const float*)d_in[10];
    const float* db0   = (const float*)d_in[11];
    const float* dW1   = (const float*)d_in[12];
    const float* db1   = (const float*)d_in[13];
    const float* dW2   = (const float*)d_in[14];
    const float* db2   = (const float*)d_in[15];
    const float* dW3   = (const float*)d_in[16];
    const float* db3   = (const float*)d_in[17];
    float* out = (float*)d_out;

    cudaFuncSetAttribute(scan_kernel, cudaFuncAttributeMaxDynamicSharedMemorySize,
                         SCAN_SMEM_BYTES);

    void *p_rssm, *p_a0, *p_a1, *p_dist;
    cudaGetSymbolAddress(&p_rssm, g_rssm);
    cudaGetSymbolAddress(&p_a0, g_a0);
    cudaGetSymbolAddress(&p_a1, g_a1);
    cudaGetSymbolAddress(&p_dist, g_dist);

    init_state_kernel<<<64, 256>>>();
    transpose_x_kernel<<<dim3(T_, I_ / 64), TPB>>>(x);
    scan_kernel<<<GBLK, TPB, SCAN_SMEM_BYTES>>>(W_ih, W_hh, b_ih, b_hh,
                                                Wm, bm, Wv, bv, noise);

    const int M = B_ * T_;  // 16384
    gemm_bias_act_kernel<<<dim3(H_ / GN, M / GM), 256>>>(
        (const float*)p_rssm, dW0, db0, (float*)p_a0, M, H_, R_, 1);
    gemm_bias_act_kernel<<<dim3(H_ / GN, M / GM), 256>>>(
        (const float*)p_a0, dW1, db1, (float*)p_a1, M, H_, H_, 1);
    gemm_bias_act_kernel<<<dim3(H_ / GN, M / GM), 256>>>(
        (const float*)p_a1, dW2, db2, (float*)p_a0, M, H_, H_, 1);
    gemm_bias_act_kernel<<<dim3(I_ / GN, M / GM), 256>>>(
        (const float*)p_a0, dW3, db3, (float*)p_dist, M, I_, H_, 0);

    epilogue_kernel<<<(B_ * T_ * I_ + 255) / 256, 256>>>(x, out);
}

// round 6
// speedup vs baseline: 1.0270x; 1.0270x over previous
#include <cuda_runtime.h>
#include <math.h>

// ---------------------------------------------------------------------------
// Problem dims
// ---------------------------------------------------------------------------
#define B_ 64
#define T_ 256
#define I_ 512
#define S_ 256
#define D_ 1024
#define H_ 1024
#define R_ 1280          // D_ + S_

#define GBLK 128         // persistent blocks; 1 block/SM, all co-resident
#define TPB  256
#define JPB  8           // D_/GBLK h-columns per block
#define SPB  2           // S_/GBLK z-columns per block

typedef unsigned long long ull;

// Shared memory layout (floats)
#define N_WHH (JPB * 3 * D_)          // 24576
#define N_WIH (JPB * 3 * S_)          // 6144
#define N_WMV (SPB * 2 * (I_ + D_))   // 6144
#define N_STG 8192                    // one staging chunk: 128 k x 64 b
#define OFF_WIH  (N_WHH)
#define OFF_WMV  (OFF_WIH + N_WIH)
#define OFF_STGA (OFF_WMV + N_WMV)                // 36864
#define OFF_STGB (OFF_STGA + N_STG)               // 45056
#define OFF_B    (OFF_STGB + N_STG)               // 53248
#define SCAN_SMEM_FLOATS (OFF_B + 64)             // 53312
#define SCAN_SMEM_BYTES  (SCAN_SMEM_FLOATS * 4)   // 213,248 B

// ---------------------------------------------------------------------------
// Device-global scratch.
// Activations use a k-PAIRED batch-last layout:
//   element (k, b) lives at float offset (k>>1)*128 + b*2 + (k&1)
// so one 8-byte load yields the (even k, odd k) pair for batch b.
// ---------------------------------------------------------------------------
__device__ __align__(256) float g_h[2][D_ * B_];     // paired layout, ping-pong
__device__ __align__(256) float g_z[2][S_ * B_];     // paired layout, ping-pong
__device__ __align__(256) float g_xT[(size_t)T_ * I_ * B_];  // per-t paired layout
__device__ __align__(256) float g_rssm[(size_t)B_ * T_ * R_]; // [b][t][1280]
__device__ __align__(256) float g_a0[(size_t)B_ * T_ * H_];
__device__ __align__(256) float g_a1[(size_t)B_ * T_ * H_];
__device__ __align__(256) float g_dist[(size_t)B_ * T_ * I_];

__device__ unsigned g_bar_count;
__device__ volatile unsigned g_bar_sense;

// ---------------------------------------------------------------------------
// Packed-f32x2 helpers (sm_100+): one FFMA2 = 2 independent fp32 FMAs
// ---------------------------------------------------------------------------
__device__ __forceinline__ void ffma2(ull& d, ull a, ull b) {
    asm("fma.rn.f32x2 %0, %1, %2, %0;" : "+l"(d) : "l"(a), "l"(b));
}
__device__ __forceinline__ float sum2(ull v) {
    return __uint_as_float((unsigned)v) + __uint_as_float((unsigned)(v >> 32));
}
__device__ __forceinline__ ull packf2(float lo, float hi) {
    return (ull)__float_as_uint(lo) | ((ull)__float_as_uint(hi) << 32);
}

// ---------------------------------------------------------------------------
// Software grid barrier (sense-reversal). All GBLK blocks co-resident.
// ---------------------------------------------------------------------------
__device__ __forceinline__ void grid_sync() {
    __syncthreads();
    if (threadIdx.x == 0) {
        __threadfence();
        unsigned sense = g_bar_sense;
        unsigned prev = atomicAdd(&g_bar_count, 1u);
        if (prev == GBLK - 1) {
            g_bar_count = 0;
            __threadfence();
            g_bar_sense = sense + 1;
        } else {
            while (g_bar_sense == sense) { __nanosleep(64); }
        }
        __threadfence();
    }
    __syncthreads();
}

// Prefetch one 8192-float chunk into registers (L1-bypassing: data is
// written by other blocks within this kernel).
__device__ __forceinline__ void pfetch(float4* pf, const float4* src) {
    const int t = threadIdx.x;
#pragma unroll
    for (int i = 0; i < 8; i++) pf[i] = __ldcg(src + t + i * TPB);
}
__device__ __forceinline__ void commitS(float4* dst, const float4* pf) {
    const int t = threadIdx.x;
#pragma unroll
    for (int i = 0; i < 8; i++) dst[t + i * TPB] = pf[i];
}

// ---------------------------------------------------------------------------
// Inner products over one 128-k chunk, 6 rows (GRU) / 2 rows (posterior).
// Accumulators are packed (even-k, odd-k) partial sums.
// ---------------------------------------------------------------------------
__device__ __forceinline__ void chunk6(const ull* __restrict__ stg,
                                       const float* __restrict__ w, int rs, int off,
                                       int r0i, int r1i, int b,
                                       ull& A0, ull& A1, ull& A2,
                                       ull& A3, ull& A4, ull& A5) {
    const ulonglong2* w0 = (const ulonglong2*)(w + (size_t)(r0i + 0) * rs + off);
    const ulonglong2* w1 = (const ulonglong2*)(w + (size_t)(r0i + 1) * rs + off);
    const ulonglong2* w2 = (const ulonglong2*)(w + (size_t)(r0i + 2) * rs + off);
    const ulonglong2* w3 = (const ulonglong2*)(w + (size_t)(r1i + 0) * rs + off);
    const ulonglong2* w4 = (const ulonglong2*)(w + (size_t)(r1i + 1) * rs + off);
    const ulonglong2* w5 = (const ulonglong2*)(w + (size_t)(r1i + 2) * rs + off);
#pragma unroll
    for (int k = 0; k < 32; ++k) {
        ull ha = stg[(2 * k) * 64 + b];
        ull hb = stg[(2 * k + 1) * 64 + b];
        ulonglong2 q;
        q = w0[k]; ffma2(A0, q.x, ha); ffma2(A0, q.y, hb);
        q = w1[k]; ffma2(A1, q.x, ha); ffma2(A1, q.y, hb);
        q = w2[k]; ffma2(A2, q.x, ha); ffma2(A2, q.y, hb);
        q = w3[k]; ffma2(A3, q.x, ha); ffma2(A3, q.y, hb);
        q = w4[k]; ffma2(A4, q.x, ha); ffma2(A4, q.y, hb);
        q = w5[k]; ffma2(A5, q.x, ha); ffma2(A5, q.y, hb);
    }
}

__device__ __forceinline__ void chunk2(const ull* __restrict__ stg,
                                       const float* __restrict__ wmv, int off,
                                       int sl, int b, ull& M, ull& V) {
    const ulonglong2* wm = (const ulonglong2*)(wmv + (size_t)(sl * 2 + 0) * 1536 + off);
    const ulonglong2* wv = (const ulonglong2*)(wmv + (size_t)(sl * 2 + 1) * 1536 + off);
#pragma unroll
    for (int k = 0; k < 32; ++k) {
        ull ha = stg[(2 * k) * 64 + b];
        ull hb = stg[(2 * k + 1) * 64 + b];
        ulonglong2 q;
        q = wm[k]; ffma2(M, q.x, ha); ffma2(M, q.y, hb);
        q = wv[k]; ffma2(V, q.x, ha); ffma2(V, q.y, hb);
    }
}

// ---------------------------------------------------------------------------
// Init: zero the t=0 recurrent state
// ---------------------------------------------------------------------------
__global__ void init_state_kernel() {
    const int stride = gridDim.x * blockDim.x;
    for (int i = blockIdx.x * blockDim.x + threadIdx.x; i < D_ * B_; i += stride)
        g_h[0][i] = 0.f;
    for (int i = blockIdx.x * blockDim.x + threadIdx.x; i < S_ * B_; i += stride)
        g_z[0][i] = 0.f;
}

// ---------------------------------------------------------------------------
// Transpose x[b][t][i] -> paired layout g_xT[t][(i>>1)*128 + b*2 + (i&1)]
// ---------------------------------------------------------------------------
__global__ void transpose_x_kernel(const float* __restrict__ x) {
    __shared__ float tile[64][65];
    const int t = blockIdx.x;
    const int c0 = blockIdx.y * 64;
    for (int l = threadIdx.x; l < 4096; l += TPB) {
        int b = l >> 6, c = l & 63;
        tile[b][c] = x[((size_t)b * T_ + t) * I_ + c0 + c];
    }
    __syncthreads();
    for (int l = threadIdx.x; l < 4096; l += TPB) {
        int c = l >> 6, b = l & 63;
        int k = c0 + c;
        g_xT[(size_t)t * I_ * 64 + (size_t)(k >> 1) * 128 + b * 2 + (k & 1)] = tile[b][c];
    }
}

// ---------------------------------------------------------------------------
// Persistent scan kernel
// ---------------------------------------------------------------------------
__global__ void __launch_bounds__(TPB, 1) scan_kernel(
    const float* __restrict__ W_ih, const float* __restrict__ W_hh,
    const float* __restrict__ b_ih, const float* __restrict__ b_hh,
    const float* __restrict__ Wm,   const float* __restrict__ bm,
    const float* __restrict__ Wv,   const float* __restrict__ bv,
    const float* __restrict__ noise)
{
    extern __shared__ float sm[];
    float* s_whh = sm;
    float* s_wih = sm + OFF_WIH;
    float* s_wmv = sm + OFF_WMV;
    float* s_stgA = sm + OFF_STGA;
    float* s_stgB = sm + OFF_STGB;
    float* s_bih = sm + OFF_B;
    float* s_bhh = sm + OFF_B + 24;
    float* s_bmv = sm + OFF_B + 48;

    const int tid = threadIdx.x;
    const int bid = blockIdx.x;
    const int j0g = bid * JPB;
    const int s0g = bid * SPB;

    // ---- load weight slices into smem (row-major, contiguous k) ----
    for (int row = 0; row < JPB * 3; ++row) {
        int jl = row / 3, g = row % 3;
        const float4* src = (const float4*)(W_hh + (size_t)(g * D_ + j0g + jl) * D_);
        float4* dst = (float4*)(s_whh + row * D_);
        dst[tid] = src[tid];
    }
    for (int row = 0; row < JPB * 3; ++row) {
        int jl = row / 3, g = row % 3;
        const float4* src = (const float4*)(W_ih + (size_t)(g * D_ + j0g + jl) * S_);
        float4* dst = (float4*)(s_wih + row * S_);
        if (tid < 64) dst[tid] = src[tid];
    }
    for (int row = 0; row < SPB * 2; ++row) {
        int sl = row >> 1, mv = row & 1;
        const float* W = mv ? Wv : Wm;
        const float4* src = (const float4*)(W + (size_t)(s0g + sl) * (I_ + D_));
        float4* dst = (float4*)(s_wmv + row * (I_ + D_));
        for (int v = tid; v < 384; v += TPB) dst[v] = src[v];
    }
    if (tid < 24) {
        int jl = tid / 3, g = tid % 3;
        s_bih[tid] = b_ih[g * D_ + j0g + jl];
        s_bhh[tid] = b_hh[g * D_ + j0g + jl];
    }
    if (tid < 2) { s_bmv[tid * 2 + 0] = bm[s0g + tid]; s_bmv[tid * 2 + 1] = bv[s0g + tid]; }
    __syncthreads();

    const int grp = tid >> 6;       // 0..3
    const int b   = tid & 63;
    const int jl0 = grp * 2, jl1 = grp * 2 + 1;
    const int r0i = jl0 * 3, r1i = jl1 * 3;
    const int sl  = (tid >> 6) & 1; // valid when tid < 128

    float4 pf[8];

    for (int t = 0; t < T_; ++t) {
        const int p = t & 1, pn = p ^ 1;
        const float4* zp4 = (const float4*)g_z[p];
        const float4* hp4 = (const float4*)g_h[p];
        const float4* hn4 = (const float4*)g_h[pn];
        const float4* x4  = (const float4*)(g_xT + (size_t)t * I_ * 64);

        ull aR0 = 0, aZ0 = 0, aNi0 = 0, aNh0 = 0;
        ull aR1 = 0, aZ1 = 0, aNi1 = 0, aNh1 = 0;

        pfetch(pf, zp4);  // first chunk: latency exposed (fresh after grid sync)
        long long hp_pair = __ldcg((const long long*)g_h[p] +
                                   (size_t)((j0g + jl0) >> 1) * 64 + b);

        // ---- gi chunks (K = 256) ----
        {
            commitS((float4*)s_stgA, pf); __syncthreads();
            pfetch(pf, zp4 + 2048);
            chunk6((const ull*)s_stgA, s_wih, S_, 0, r0i, r1i, b,
                   aR0, aZ0, aNi0, aR1, aZ1, aNi1);
            commitS((float4*)s_stgB, pf); __syncthreads();
            pfetch(pf, hp4);
            chunk6((const ull*)s_stgB, s_wih, S_, 128, r0i, r1i, b,
                   aR0, aZ0, aNi0, aR1, aZ1, aNi1);
        }
        // ---- gh chunks (K = 1024) ----
        for (int c = 0; c < 8; ++c) {
            float* buf = (c & 1) ? s_stgB : s_stgA;
            commitS((float4*)buf, pf); __syncthreads();
            if (c < 7) pfetch(pf, hp4 + (c + 1) * 2048);
            else       pfetch(pf, x4);
            chunk6((const ull*)buf, s_whh, D_, c * 128, r0i, r1i, b,
                   aR0, aZ0, aNh0, aR1, aZ1, aNh1);
        }

        // ---- finalize h ----
        {
            float vr0 = sum2(aR0) + s_bih[r0i + 0] + s_bhh[r0i + 0];
            float vz0 = sum2(aZ0) + s_bih[r0i + 1] + s_bhh[r0i + 1];
            float gi0 = sum2(aNi0) + s_bih[r0i + 2];
            float gh0 = sum2(aNh0) + s_bhh[r0i + 2];
            float vr1 = sum2(aR1) + s_bih[r1i + 0] + s_bhh[r1i + 0];
            float vz1 = sum2(aZ1) + s_bih[r1i + 1] + s_bhh[r1i + 1];
            float gi1 = sum2(aNi1) + s_bih[r1i + 2];
            float gh1 = sum2(aNh1) + s_bhh[r1i + 2];

            ull hpu = (ull)hp_pair;
            float hp0 = __uint_as_float((unsigned)hpu);
            float hp1 = __uint_as_float((unsigned)(hpu >> 32));

            float r0 = 1.f / (1.f + expf(-vr0));
            float zg0 = 1.f / (1.f + expf(-vz0));
            float n0 = tanhf(gi0 + r0 * gh0);
            float hn0 = (1.f - zg0) * n0 + zg0 * hp0;
            float r1 = 1.f / (1.f + expf(-vr1));
            float zg1 = 1.f / (1.f + expf(-vz1));
            float n1 = tanhf(gi1 + r1 * gh1);
            float hn1 = (1.f - zg1) * n1 + zg1 * hp1;

            // jl0 is even: (hn0, hn1) is exactly one k-pair
            __stcg((long long*)g_h[pn] + (size_t)((j0g + jl0) >> 1) * 64 + b,
                   (long long)packf2(hn0, hn1));
            g_rssm[((size_t)b * T_ + t) * R_ + j0g + jl0] = hn0;
            g_rssm[((size_t)b * T_ + t) * R_ + j0g + jl1] = hn1;
        }

        grid_sync();   // h_new visible

        // ---- posterior ----
        ull aM = 0, aV = 0;
        for (int c = 0; c < 4; ++c) {            // x part (K = 512)
            float* buf = (c & 1) ? s_stgB : s_stgA;
            commitS((float4*)buf, pf); __syncthreads();
            if (c < 3) pfetch(pf, x4 + (c + 1) * 2048);
            else       pfetch(pf, hn4);          // after grid_sync: safe
            if (tid < 128)
                chunk2((const ull*)buf, s_wmv, c * 128, sl, b, aM, aV);
        }
        for (int c = 0; c < 8; ++c) {            // h part (K = 1024)
            float* buf = (c & 1) ? s_stgB : s_stgA;
            commitS((float4*)buf, pf); __syncthreads();
            if (c < 7) pfetch(pf, hn4 + (c + 1) * 2048);
            if (tid < 128)
                chunk2((const ull*)buf, s_wmv, 512 + c * 128, sl, b, aM, aV);
        }
        if (tid < 128) {
            float m = sum2(aM) + s_bmv[sl * 2 + 0];
            float v = sum2(aV) + s_bmv[sl * 2 + 1];
            int sg = s0g + sl;
            float nz = noise[((size_t)t * B_ + b) * S_ + sg];
            float zval = nz * expf(0.5f * v) + m;
            __stcg(&g_z[pn][(size_t)(sg >> 1) * 128 + b * 2 + (sg & 1)], zval);
            g_rssm[((size_t)b * T_ + t) * R_ + D_ + sg] = zval;
        }

        grid_sync();   // z_new visible
    }
}

// ---------------------------------------------------------------------------
// Decoder GEMM with packed-f32x2 accumulation.
// C[M,N] = act(A[M,K] @ W[N,K]^T + bias). Block tile 128x64, thread 8x4.
// Accumulators hold (even-k, odd-k) partial sums; summed in epilogue.
// ---------------------------------------------------------------------------
#define GM 128
#define GN 64
#define GK 16

__global__ void __launch_bounds__(256, 2) gemm_f32x2_kernel(
    const float* __restrict__ A, const float* __restrict__ W,
    const float* __restrict__ bias, float* __restrict__ C,
    int M, int N, int K, int act)
{
    __shared__ ull As2[8][GM];   // [k2][m]
    __shared__ ull Ws2[8][GN];   // [k2][swizzled n]: col = (n&3)*16 + (n>>2)
    const int tid = threadIdx.x;
    const int bm = blockIdx.y * GM;
    const int bn = blockIdx.x * GN;
    const int tx = tid & 15, ty = tid >> 4;
    const int m0 = ty * 8, n0 = tx * 4;

    const int arow0 = tid >> 2,        apart0 = tid & 3;           // i=0
    const int arow1 = (tid + 256) >> 2, apart1 = tid & 3;          // i=1
    const int wrow = tid >> 2, wpart = tid & 3;
    const int wcol = (wrow & 3) * 16 + (wrow >> 2);

    ull acc[8][4];
#pragma unroll
    for (int i = 0; i < 8; ++i)
#pragma unroll
        for (int j = 0; j < 4; ++j) acc[i][j] = 0ULL;

    float4 va0, va1, vw;
    va0 = *(const float4*)(A + (size_t)(bm + arow0) * K + apart0 * 4);
    va1 = *(const float4*)(A + (size_t)(bm + arow1) * K + apart1 * 4);
    vw  = *(const float4*)(W + (size_t)(bn + wrow) * K + wpart * 4);

    for (int kb = 0; kb < K; kb += GK) {
        As2[apart0 * 2 + 0][arow0] = packf2(va0.x, va0.y);
        As2[apart0 * 2 + 1][arow0] = packf2(va0.z, va0.w);
        As2[apart1 * 2 + 0][arow1] = packf2(va1.x, va1.y);
        As2[apart1 * 2 + 1][arow1] = packf2(va1.z, va1.w);
        Ws2[wpart * 2 + 0][wcol] = packf2(vw.x, vw.y);
        Ws2[wpart * 2 + 1][wcol] = packf2(vw.z, vw.w);
        __syncthreads();
        if (kb + GK < K) {
            va0 = *(const float4*)(A + (size_t)(bm + arow0) * K + kb + GK + apart0 * 4);
            va1 = *(const float4*)(A + (size_t)(bm + arow1) * K + kb + GK + apart1 * 4);
            vw  = *(const float4*)(W + (size_t)(bn + wrow) * K + kb + GK + wpart * 4);
        }
#pragma unroll
        for (int k2 = 0; k2 < 8; ++k2) {
            ull ra[8], rw[4];
#pragma unroll
            for (int i = 0; i < 8; ++i) ra[i] = As2[k2][m0 + i];
#pragma unroll
            for (int j = 0; j < 4; ++j) rw[j] = Ws2[k2][j * 16 + tx];
#pragma unroll
            for (int i = 0; i < 8; ++i)
#pragma unroll
                for (int j = 0; j < 4; ++j) ffma2(acc[i][j], ra[i], rw[j]);
        }
        __syncthreads();
    }

    float bb[4];
#pragma unroll
    for (int j = 0; j < 4; ++j) bb[j] = bias[bn + n0 + j];
#pragma unroll
    for (int i = 0; i < 8; ++i) {
        float r[4];
#pragma unroll
        for (int j = 0; j < 4; ++j) {
            float v = sum2(acc[i][j]) + bb[j];
            r[j] = act ? (v > 0.f ? v : expm1f(v)) : v;
        }
        *(float4*)(C + (size_t)(bm + m0 + i) * N + bn + n0) =
            make_float4(r[0], r[1], r[2], r[3]);
    }
}

// ---------------------------------------------------------------------------
// Epilogue: build (x_delta_hat, x_hat) into d_out
// ---------------------------------------------------------------------------
__global__ void epilogue_kernel(const float* __restrict__ x, float* __restrict__ out) {
    size_t idx = (size_t)blockIdx.x * blockDim.x + threadIdx.x;
    const size_t total = (size_t)B_ * T_ * I_;
    if (idx >= total) return;
    int i = (int)(idx & (I_ - 1));
    size_t bt = idx >> 9;
    int t = (int)(bt & (T_ - 1));
    int b = (int)(bt >> 8);

    float xh;
    if (t == 0) xh = x[idx];
    else        xh = x[idx - I_] + g_dist[idx - I_];
    out[(size_t)B_ * (T_ - 1) * I_ + idx] = xh;

    if (t < T_ - 1)
        out[((size_t)b * (T_ - 1) + t) * I_ + i] = g_dist[idx];
}

// ---------------------------------------------------------------------------
// kernel_launch
// ---------------------------------------------------------------------------
extern "C" void kernel_launch(void* const* d_in, const int* in_sizes, int n_in,
                              void* d_out, int out_size) {
    const float* x     = (const float*)d_in[0];
    const float* noise = (const float*)d_in[1];
    const float* W_ih  = (const float*)d_in[2];
    const float* W_hh  = (const float*)d_in[3];
    const float* b_ih  = (const float*)d_in[4];
    const float* b_hh  = (const float*)d_in[5];
    const float* Wm    = (const float*)d_in[6];
    const float* bm    = (const float*)d_in[7];
    const float* Wv    = (const float*)d_in[8];
    const float* bv    = (const float*)d_in[9];
    const float* dW0   = (const float*)d_in[10];
    const float* db0   = (const float*)d_in[11];
    const float* dW1   = (const float*)d_in[12];
    const float* db1   = (const float*)d_in[13];
    const float* dW2   = (const float*)d_in[14];
    const float* db2   = (const float*)d_in[15];
    const float* dW3   = (const float*)d_in[16];
    const float* db3   = (const float*)d_in[17];
    float* out = (float*)d_out;

    cudaFuncSetAttribute(scan_kernel, cudaFuncAttributeMaxDynamicSharedMemorySize,
                         SCAN_SMEM_BYTES);

    void *p_rssm, *p_a0, *p_a1, *p_dist;
    cudaGetSymbolAddress(&p_rssm, g_rssm);
    cudaGetSymbolAddress(&p_a0, g_a0);
    cudaGetSymbolAddress(&p_a1, g_a1);
    cudaGetSymbolAddress(&p_dist, g_dist);

    init_state_kernel<<<64, 256>>>();
    transpose_x_kernel<<<dim3(T_, I_ / 64), TPB>>>(x);
    scan_kernel<<<GBLK, TPB, SCAN_SMEM_BYTES>>>(W_ih, W_hh, b_ih, b_hh,
                                                Wm, bm, Wv, bv, noise);

    const int M = B_ * T_;  // 16384
    gemm_f32x2_kernel<<<dim3(H_ / GN, M / GM), 256>>>(
        (const float*)p_rssm, dW0, db0, (float*)p_a0, M, H_, R_, 1);
    gemm_f32x2_kernel<<<dim3(H_ / GN, M / GM), 256>>>(
        (const float*)p_a0, dW1, db1, (float*)p_a1, M, H_, H_, 1);
    gemm_f32x2_kernel<<<dim3(H_ / GN, M / GM), 256>>>(
        (const float*)p_a1, dW2, db2, (float*)p_a0, M, H_, H_, 1);
    gemm_f32x2_kernel<<<dim3(I_ / GN, M / GM), 256>>>(
        (const float*)p_a0, dW3, db3, (float*)p_dist, M, I_, H_, 0);

    epilogue_kernel<<<(B_ * T_ * I_ + 255) / 256, 256>>>(x, out);
}

// round 7
// speedup vs baseline: 1.1746x; 1.1437x over previous
#include <cuda_runtime.h>
#include <math.h>

// ---------------------------------------------------------------------------
// Problem dims
// ---------------------------------------------------------------------------
#define B_ 64
#define T_ 256
#define I_ 512
#define S_ 256
#define D_ 1024
#define H_ 1024
#define R_ 1280          // D_ + S_

#define GBLK 128         // persistent blocks; 1 block/SM, all co-resident
#define TPB  256
#define JPB  8           // D_/GBLK h-columns per block
#define SPB  2           // S_/GBLK z-columns per block

typedef unsigned long long ull;

// Scan shared memory layout (floats)
#define N_WHH  (24 * 1024)   // 24576
#define N_WIH  (24 * 256)    // 6144
#define N_WMVH (4 * 1024)    // 4096
#define OFF_WIH   (N_WHH)
#define OFF_WMVH  (OFF_WIH + N_WIH)          // 30720
#define OFF_STGA  (OFF_WMVH + N_WMVH)        // 34816
#define OFF_STGB  (OFF_STGA + 8192)          // 43008
#define OFF_B     (OFF_STGB + 8192)          // 51200
#define SCAN_SMEM_FLOATS (OFF_B + 64)        // 51264
#define SCAN_SMEM_BYTES  (SCAN_SMEM_FLOATS * 4)   // 205,056 B

// ---------------------------------------------------------------------------
// Device-global scratch (no runtime allocation).
// Activations (h, z) use a k-PAIRED batch-last layout:
//   element (k, b) lives at float offset (k>>1)*128 + b*2 + (k&1)
// so one 8-byte load yields the (even k, odd k) pair for batch b.
// ---------------------------------------------------------------------------
__device__ __align__(256) float g_h[D_ * B_];
__device__ __align__(256) float g_z[S_ * B_];
__device__ __align__(256) float g_wx[2 * S_ * I_];        // interleaved Wm/Wv x-part
__device__ __align__(256) float g_bx[2 * S_];
__device__ __align__(256) float g_postx[(size_t)B_ * T_ * 2 * S_]; // x-part of posterior
__device__ __align__(256) float g_rssm[(size_t)B_ * T_ * R_];      // [b][t][1280]
__device__ __align__(256) float g_a0[(size_t)B_ * T_ * H_];
__device__ __align__(256) float g_a1[(size_t)B_ * T_ * H_];
__device__ __align__(256) float g_dist[(size_t)B_ * T_ * I_];

__device__ unsigned g_arrive[GBLK * 32];   // one 128B line per block
__device__ unsigned g_release;

// ---------------------------------------------------------------------------
// Packed-f32x2 helpers (sm_100+): one FFMA2 = 2 independent fp32 FMAs
// ---------------------------------------------------------------------------
__device__ __forceinline__ void ffma2(ull& d, ull a, ull b) {
    asm("fma.rn.f32x2 %0, %1, %2, %0;" : "+l"(d) : "l"(a), "l"(b));
}
__device__ __forceinline__ float sum2(ull v) {
    return __uint_as_float((unsigned)v) + __uint_as_float((unsigned)(v >> 32));
}
__device__ __forceinline__ ull packf2(float lo, float hi) {
    return (ull)__float_as_uint(lo) | ((ull)__float_as_uint(hi) << 32);
}

// ---------------------------------------------------------------------------
// Grid barrier: per-block arrival flags polled in parallel by block 0,
// single release word. acquire/release for ordering. Tokens are monotonic
// within one launch; init kernel zeroes state each launch (graph-replay safe).
// ---------------------------------------------------------------------------
__device__ __forceinline__ void grid_sync(unsigned token) {
    __syncthreads();
    if (blockIdx.x == 0) {
        if (threadIdx.x > 0 && threadIdx.x < GBLK) {
            unsigned v;
            do {
                asm volatile("ld.acquire.gpu.global.u32 %0, [%1];"
                             : "=r"(v) : "l"(g_arrive + threadIdx.x * 32) : "memory");
            } while (v < token);
        }
        __syncthreads();
        if (threadIdx.x == 0) {
            asm volatile("st.release.gpu.global.u32 [%0], %1;"
                         :: "l"(&g_release), "r"(token) : "memory");
        }
    } else {
        if (threadIdx.x == 0) {
            asm volatile("st.release.gpu.global.u32 [%0], %1;"
                         :: "l"(g_arrive + blockIdx.x * 32), "r"(token) : "memory");
            unsigned v;
            do {
                asm volatile("ld.acquire.gpu.global.u32 %0, [%1];"
                             : "=r"(v) : "l"(&g_release) : "memory");
            } while (v < token);
        }
        __syncthreads();
    }
}

// Prefetch one 8192-float chunk into registers (L1-bypassing: cross-SM data).
__device__ __forceinline__ void pfetch(float4* pf, const float4* src) {
    const int t = threadIdx.x;
#pragma unroll
    for (int i = 0; i < 8; i++) pf[i] = __ldcg(src + t + i * TPB);
}
__device__ __forceinline__ void commitS(float4* dst, const float4* pf) {
    const int t = threadIdx.x;
#pragma unroll
    for (int i = 0; i < 8; i++) dst[t + i * TPB] = pf[i];
}

// ---------------------------------------------------------------------------
// Inner products over one 128-k chunk.
// chunk6: 6 GRU rows.  chunk7: 6 GRU rows + 1 posterior row (act regs reused).
// ---------------------------------------------------------------------------
__device__ __forceinline__ void chunk6(const ull* __restrict__ stg,
                                       const float* __restrict__ w, int rs, int off,
                                       int r0i, int r1i, int b,
                                       ull& A0, ull& A1, ull& A2,
                                       ull& A3, ull& A4, ull& A5) {
    const ulonglong2* w0 = (const ulonglong2*)(w + (size_t)(r0i + 0) * rs + off);
    const ulonglong2* w1 = (const ulonglong2*)(w + (size_t)(r0i + 1) * rs + off);
    const ulonglong2* w2 = (const ulonglong2*)(w + (size_t)(r0i + 2) * rs + off);
    const ulonglong2* w3 = (const ulonglong2*)(w + (size_t)(r1i + 0) * rs + off);
    const ulonglong2* w4 = (const ulonglong2*)(w + (size_t)(r1i + 1) * rs + off);
    const ulonglong2* w5 = (const ulonglong2*)(w + (size_t)(r1i + 2) * rs + off);
#pragma unroll
    for (int k = 0; k < 32; ++k) {
        ull ha = stg[(2 * k) * 64 + b];
        ull hb = stg[(2 * k + 1) * 64 + b];
        ulonglong2 q;
        q = w0[k]; ffma2(A0, q.x, ha); ffma2(A0, q.y, hb);
        q = w1[k]; ffma2(A1, q.x, ha); ffma2(A1, q.y, hb);
        q = w2[k]; ffma2(A2, q.x, ha); ffma2(A2, q.y, hb);
        q = w3[k]; ffma2(A3, q.x, ha); ffma2(A3, q.y, hb);
        q = w4[k]; ffma2(A4, q.x, ha); ffma2(A4, q.y, hb);
        q = w5[k]; ffma2(A5, q.x, ha); ffma2(A5, q.y, hb);
    }
}

__device__ __forceinline__ void chunk7(const ull* __restrict__ stg,
                                       const float* __restrict__ whh, int off,
                                       int r0i, int r1i,
                                       const float* __restrict__ wp_row, int b,
                                       ull& A0, ull& A1, ull& A2,
                                       ull& A3, ull& A4, ull& A5, ull& PV) {
    const ulonglong2* w0 = (const ulonglong2*)(whh + (size_t)(r0i + 0) * D_ + off);
    const ulonglong2* w1 = (const ulonglong2*)(whh + (size_t)(r0i + 1) * D_ + off);
    const ulonglong2* w2 = (const ulonglong2*)(whh + (size_t)(r0i + 2) * D_ + off);
    const ulonglong2* w3 = (const ulonglong2*)(whh + (size_t)(r1i + 0) * D_ + off);
    const ulonglong2* w4 = (const ulonglong2*)(whh + (size_t)(r1i + 1) * D_ + off);
    const ulonglong2* w5 = (const ulonglong2*)(whh + (size_t)(r1i + 2) * D_ + off);
    const ulonglong2* wp = (const ulonglong2*)(wp_row + off);
#pragma unroll
    for (int k = 0; k < 32; ++k) {
        ull ha = stg[(2 * k) * 64 + b];
        ull hb = stg[(2 * k + 1) * 64 + b];
        ulonglong2 q;
        q = w0[k]; ffma2(A0, q.x, ha); ffma2(A0, q.y, hb);
        q = w1[k]; ffma2(A1, q.x, ha); ffma2(A1, q.y, hb);
        q = w2[k]; ffma2(A2, q.x, ha); ffma2(A2, q.y, hb);
        q = w3[k]; ffma2(A3, q.x, ha); ffma2(A3, q.y, hb);
        q = w4[k]; ffma2(A4, q.x, ha); ffma2(A4, q.y, hb);
        q = w5[k]; ffma2(A5, q.x, ha); ffma2(A5, q.y, hb);
        q = wp[k]; ffma2(PV, q.x, ha); ffma2(PV, q.y, hb);
    }
}

// ---------------------------------------------------------------------------
// Init: zero recurrent state + barrier state (every launch / graph replay)
// ---------------------------------------------------------------------------
__global__ void init_state_kernel() {
    const int idx = blockIdx.x * blockDim.x + threadIdx.x;
    const int stride = gridDim.x * blockDim.x;
    for (int i = idx; i < D_ * B_; i += stride) g_h[i] = 0.f;
    for (int i = idx; i < S_ * B_; i += stride) g_z[i] = 0.f;
    for (int i = idx; i < GBLK * 32; i += stride) g_arrive[i] = 0u;
    if (idx == 0) g_release = 0u;
}

// ---------------------------------------------------------------------------
// Build interleaved x-part posterior weight [2S][I] and bias (n = 2s+mv)
// ---------------------------------------------------------------------------
__global__ void build_wx_kernel(const float* __restrict__ Wm,
                                const float* __restrict__ Wv,
                                const float* __restrict__ bm,
                                const float* __restrict__ bv) {
    const int n = blockIdx.x;            // 0..511
    const int s = n >> 1, mv = n & 1;
    const float* src = (mv ? Wv : Wm) + (size_t)s * (I_ + D_);
    float* dst = g_wx + (size_t)n * I_;
    for (int k = threadIdx.x; k < I_; k += blockDim.x) dst[k] = src[k];
    if (threadIdx.x == 0) g_bx[n] = mv ? bv[s] : bm[s];
}

// ---------------------------------------------------------------------------
// Persistent scan: 256 steps, 2 grid syncs/step, 10 staged chunks/step.
// Step layout:
//   (A) z-pass (2 chunks)  -> gi_t;  finalize h_t (uses gh_t from prev (B))
//   sync;  (B) h-pass (8 chunks) -> gh_{t+1} AND posterior h-part of t
//   finalize z_t (with precomputed x-part);  sync
// ---------------------------------------------------------------------------
__global__ void __launch_bounds__(TPB, 1) scan_kernel(
    const float* __restrict__ W_ih, const float* __restrict__ W_hh,
    const float* __restrict__ b_ih, const float* __restrict__ b_hh,
    const float* __restrict__ Wm,   const float* __restrict__ Wv,
    const float* __restrict__ noise)
{
    extern __shared__ float sm[];
    float* s_whh  = sm;
    float* s_wih  = sm + OFF_WIH;
    float* s_wmvh = sm + OFF_WMVH;
    float* s_stgA = sm + OFF_STGA;
    float* s_stgB = sm + OFF_STGB;
    float* s_bih  = sm + OFF_B;
    float* s_bhh  = sm + OFF_B + 24;

    const int tid = threadIdx.x;
    const int bid = blockIdx.x;
    const int j0g = bid * JPB;
    const int s0g = bid * SPB;

    // ---- weight slices into smem (once; amortized over 256 steps) ----
    for (int row = 0; row < 24; ++row) {
        int jl = row / 3, g = row % 3;
        const float4* src = (const float4*)(W_hh + (size_t)(g * D_ + j0g + jl) * D_);
        ((float4*)(s_whh + row * D_))[tid] = src[tid];
    }
    for (int row = 0; row < 24; ++row) {
        int jl = row / 3, g = row % 3;
        const float4* src = (const float4*)(W_ih + (size_t)(g * D_ + j0g + jl) * S_);
        if (tid < 64) ((float4*)(s_wih + row * S_))[tid] = src[tid];
    }
    for (int row = 0; row < 4; ++row) {   // row = 2*sl + mv, h-part columns
        int sl = row >> 1, mv = row & 1;
        const float* W = (mv ? Wv : Wm) + (size_t)(s0g + sl) * (I_ + D_) + I_;
        ((float4*)(s_wmvh + row * D_))[tid] = ((const float4*)W)[tid];
    }
    if (tid < 24) {
        int jl = tid / 3, g = tid % 3;
        s_bih[tid] = b_ih[g * D_ + j0g + jl];
        s_bhh[tid] = b_hh[g * D_ + j0g + jl];
    }
    __syncthreads();

    const int grp = tid >> 6;       // 0..3  -> posterior row (sl = grp>>1, mv = grp&1)
    const int b   = tid & 63;
    const int jl0 = grp * 2, jl1 = grp * 2 + 1;
    const int r0i = jl0 * 3, r1i = jl1 * 3;
    const float* wp_row = s_wmvh + grp * D_;

    const float4* z4 = (const float4*)g_z;
    const float4* h4 = (const float4*)g_h;

    float4 pf[8];
    float hp0 = 0.f, hp1 = 0.f;                      // register-carried h_prev
    ull ghr0 = 0, ghz0 = 0, ghn0 = 0, ghr1 = 0, ghz1 = 0, ghn1 = 0;

    pfetch(pf, z4);                                   // z_{-1} = zeros

    for (int t = 0; t < T_; ++t) {
        // prefetch posterior x-part + noise (needed at end of (B))
        float px = __ldcg(g_postx + (size_t)(b * T_ + t) * (2 * S_) + 2 * s0g + grp);
        float nz = __ldcg(noise + ((size_t)t * B_ + b) * S_ + s0g + (grp >> 1));

        // ================= (A) z-pass: gi over z_{t-1} (2 chunks) ==========
        ull gir0 = 0, giz0 = 0, gin0 = 0, gir1 = 0, giz1 = 0, gin1 = 0;
        {
            commitS((float4*)s_stgA, pf); __syncthreads();
            pfetch(pf, z4 + 2048);
            chunk6((const ull*)s_stgA, s_wih, S_, 0, r0i, r1i, b,
                   gir0, giz0, gin0, gir1, giz1, gin1);
            commitS((float4*)s_stgB, pf); __syncthreads();
            chunk6((const ull*)s_stgB, s_wih, S_, 128, r0i, r1i, b,
                   gir0, giz0, gin0, gir1, giz1, gin1);
        }

        // ---- finalize h_t ----
        {
            float vr0 = sum2(gir0) + sum2(ghr0) + s_bih[r0i + 0] + s_bhh[r0i + 0];
            float vz0 = sum2(giz0) + sum2(ghz0) + s_bih[r0i + 1] + s_bhh[r0i + 1];
            float gi0 = sum2(gin0) + s_bih[r0i + 2];
            float gh0 = sum2(ghn0) + s_bhh[r0i + 2];
            float vr1 = sum2(gir1) + sum2(ghr1) + s_bih[r1i + 0] + s_bhh[r1i + 0];
            float vz1 = sum2(giz1) + sum2(ghz1) + s_bih[r1i + 1] + s_bhh[r1i + 1];
            float gi1 = sum2(gin1) + s_bih[r1i + 2];
            float gh1 = sum2(ghn1) + s_bhh[r1i + 2];

            float r0 = 1.f / (1.f + expf(-vr0));
            float zg0 = 1.f / (1.f + expf(-vz0));
            float n0 = tanhf(gi0 + r0 * gh0);
            float hn0 = (1.f - zg0) * n0 + zg0 * hp0;
            float r1 = 1.f / (1.f + expf(-vr1));
            float zg1 = 1.f / (1.f + expf(-vz1));
            float n1 = tanhf(gi1 + r1 * gh1);
            float hn1 = (1.f - zg1) * n1 + zg1 * hp1;
            hp0 = hn0; hp1 = hn1;

            // (jl0 even): (hn0, hn1) is exactly one k-pair in paired layout
            __stcg((long long*)g_h + (size_t)((j0g + jl0) >> 1) * 64 + b,
                   (long long)packf2(hn0, hn1));
            __stcg((float2*)(g_rssm + ((size_t)b * T_ + t) * R_ + j0g + jl0),
                   make_float2(hn0, hn1));
        }

        grid_sync(2 * t + 1);     // h_t visible everywhere
        pfetch(pf, h4);           // exposed latency (unavoidable after sync)

        // ====== (B) h-pass over h_t: gh_{t+1} + posterior h-part (8 chunks) ==
        ghr0 = 0; ghz0 = 0; ghn0 = 0; ghr1 = 0; ghz1 = 0; ghn1 = 0;
        ull pv = 0;
        for (int c = 0; c < 8; ++c) {
            float* buf = (c & 1) ? s_stgB : s_stgA;
            commitS((float4*)buf, pf); __syncthreads();
            if (c < 7) pfetch(pf, h4 + (c + 1) * 2048);
            chunk7((const ull*)buf, s_whh, c * 128, r0i, r1i, wp_row, b,
                   ghr0, ghz0, ghn0, ghr1, ghz1, ghn1, pv);
        }

        // ---- finalize z_t: combine m/v across grp pairs via smem ----
        {
            float my = sum2(pv) + px;          // px includes x-part + bias
            s_stgA[grp * 64 + b] = my;         // bufA free (last chunk used bufB)
            __syncthreads();
            if ((grp & 1) == 0) {
                float m = s_stgA[grp * 64 + b];
                float v = s_stgA[(grp + 1) * 64 + b];
                float zv = nz * expf(0.5f * v) + m;
                int sg = s0g + (grp >> 1);
                __stcg(&g_z[(size_t)(sg >> 1) * 128 + b * 2 + (sg & 1)], zv);
                g_rssm[((size_t)b * T_ + t) * R_ + D_ + sg] = zv;
            }
        }

        grid_sync(2 * t + 2);     // z_t visible everywhere
        pfetch(pf, z4);           // next step's first chunk
    }
}

// ---------------------------------------------------------------------------
// Decoder GEMM, packed-f32x2, GK=32, double-buffered smem (1 sync per k-tile).
// C[M,N] = act(A[M,K] @ W[N,K]^T + bias). Block tile 128x64, thread 8x4.
// ---------------------------------------------------------------------------
#define GM 128
#define GN 64
#define GK 32
#define KK2 (GK / 2)

__global__ void __launch_bounds__(256, 2) gemm_f32x2_kernel(
    const float* __restrict__ A, const float* __restrict__ W,
    const float* __restrict__ bias, float* __restrict__ C,
    int M, int N, int K, int act)
{
    __shared__ ull As2[2][KK2][GM];   // 32 KB
    __shared__ ull Ws2[2][KK2][GN];   // 16 KB  (total 48 KB static)
    const int tid = threadIdx.x;
    const int bm = blockIdx.y * GM;
    const int bn = blockIdx.x * GN;
    const int tx = tid & 15, ty = tid >> 4;
    const int m0 = ty * 8, n0 = tx * 4;

    const int part = tid & 7;      // which float4 within the 32-k row segment
    const int lrow = tid >> 3;     // 0..31

    ull acc[8][4];
#pragma unroll
    for (int i = 0; i < 8; ++i)
#pragma unroll
        for (int j = 0; j < 4; ++j) acc[i][j] = 0ULL;

    float4 va[4], vw[2];
#pragma unroll
    for (int i = 0; i < 4; ++i)
        va[i] = *(const float4*)(A + (size_t)(bm + lrow + i * 32) * K + part * 4);
#pragma unroll
    for (int i = 0; i < 2; ++i)
        vw[i] = *(const float4*)(W + (size_t)(bn + lrow + i * 32) * K + part * 4);

#pragma unroll
    for (int i = 0; i < 4; ++i) {
        As2[0][part * 2 + 0][lrow + i * 32] = packf2(va[i].x, va[i].y);
        As2[0][part * 2 + 1][lrow + i * 32] = packf2(va[i].z, va[i].w);
    }
#pragma unroll
    for (int i = 0; i < 2; ++i) {
        Ws2[0][part * 2 + 0][lrow + i * 32] = packf2(vw[i].x, vw[i].y);
        Ws2[0][part * 2 + 1][lrow + i * 32] = packf2(vw[i].z, vw[i].w);
    }

    const int niter = K / GK;
    int buf = 0;
    for (int kb = 0; kb < niter; ++kb) {
        __syncthreads();
        if (kb + 1 < niter) {
            int ko = (kb + 1) * GK + part * 4;
#pragma unroll
            for (int i = 0; i < 4; ++i)
                va[i] = *(const float4*)(A + (size_t)(bm + lrow + i * 32) * K + ko);
#pragma unroll
            for (int i = 0; i < 2; ++i)
                vw[i] = *(const float4*)(W + (size_t)(bn + lrow + i * 32) * K + ko);
        }
#pragma unroll
        for (int k2 = 0; k2 < KK2; ++k2) {
            ull ra[8], rw[4];
            *(ulonglong2*)&ra[0] = *(const ulonglong2*)&As2[buf][k2][m0 + 0];
            *(ulonglong2*)&ra[2] = *(const ulonglong2*)&As2[buf][k2][m0 + 2];
            *(ulonglong2*)&ra[4] = *(const ulonglong2*)&As2[buf][k2][m0 + 4];
            *(ulonglong2*)&ra[6] = *(const ulonglong2*)&As2[buf][k2][m0 + 6];
            *(ulonglong2*)&rw[0] = *(const ulonglong2*)&Ws2[buf][k2][n0 + 0];
            *(ulonglong2*)&rw[2] = *(const ulonglong2*)&Ws2[buf][k2][n0 + 2];
#pragma unroll
            for (int i = 0; i < 8; ++i)
#pragma unroll
                for (int j = 0; j < 4; ++j) ffma2(acc[i][j], ra[i], rw[j]);
        }
        if (kb + 1 < niter) {
            int nb = buf ^ 1;
#pragma unroll
            for (int i = 0; i < 4; ++i) {
                As2[nb][part * 2 + 0][lrow + i * 32] = packf2(va[i].x, va[i].y);
                As2[nb][part * 2 + 1][lrow + i * 32] = packf2(va[i].z, va[i].w);
            }
#pragma unroll
            for (int i = 0; i < 2; ++i) {
                Ws2[nb][part * 2 + 0][lrow + i * 32] = packf2(vw[i].x, vw[i].y);
                Ws2[nb][part * 2 + 1][lrow + i * 32] = packf2(vw[i].z, vw[i].w);
            }
            buf = nb;
        }
    }

    float bb[4];
#pragma unroll
    for (int j = 0; j < 4; ++j) bb[j] = bias[bn + n0 + j];
#pragma unroll
    for (int i = 0; i < 8; ++i) {
        float r[4];
#pragma unroll
        for (int j = 0; j < 4; ++j) {
            float v = sum2(acc[i][j]) + bb[j];
            r[j] = act ? (v > 0.f ? v : expm1f(v)) : v;
        }
        *(float4*)(C + (size_t)(bm + m0 + i) * N + bn + n0) =
            make_float4(r[0], r[1], r[2], r[3]);
    }
}

// ---------------------------------------------------------------------------
// Epilogue: build (x_delta_hat, x_hat) into d_out
// ---------------------------------------------------------------------------
__global__ void epilogue_kernel(const float* __restrict__ x, float* __restrict__ out) {
    size_t idx = (size_t)blockIdx.x * blockDim.x + threadIdx.x;
    const size_t total = (size_t)B_ * T_ * I_;
    if (idx >= total) return;
    int i = (int)(idx & (I_ - 1));
    size_t bt = idx >> 9;
    int t = (int)(bt & (T_ - 1));
    int b = (int)(bt >> 8);

    float xh;
    if (t == 0) xh = x[idx];
    else        xh = x[idx - I_] + g_dist[idx - I_];
    out[(size_t)B_ * (T_ - 1) * I_ + idx] = xh;

    if (t < T_ - 1)
        out[((size_t)b * (T_ - 1) + t) * I_ + i] = g_dist[idx];
}

// ---------------------------------------------------------------------------
// kernel_launch
// ---------------------------------------------------------------------------
extern "C" void kernel_launch(void* const* d_in, const int* in_sizes, int n_in,
                              void* d_out, int out_size) {
    const float* x     = (const float*)d_in[0];
    const float* noise = (const float*)d_in[1];
    const float* W_ih  = (const float*)d_in[2];
    const float* W_hh  = (const float*)d_in[3];
    const float* b_ih  = (const float*)d_in[4];
    const float* b_hh  = (const float*)d_in[5];
    const float* Wm    = (const float*)d_in[6];
    // const float* bm = (const float*)d_in[7];
    const float* Wv    = (const float*)d_in[8];
    // const float* bv = (const float*)d_in[9];
    const float* bm    = (const float*)d_in[7];
    const float* bv    = (const float*)d_in[9];
    const float* dW0   = (const float*)d_in[10];
    const float* db0   = (const float*)d_in[11];
    const float* dW1   = (const float*)d_in[12];
    const float* db1   = (const float*)d_in[13];
    const float* dW2   = (const float*)d_in[14];
    const float* db2   = (const float*)d_in[15];
    const float* dW3   = (const float*)d_in[16];
    const float* db3   = (const float*)d_in[17];
    float* out = (float*)d_out;

    cudaFuncSetAttribute(scan_kernel, cudaFuncAttributeMaxDynamicSharedMemorySize,
                         SCAN_SMEM_BYTES);

    void *p_rssm, *p_a0, *p_a1, *p_dist, *p_wx, *p_bx, *p_postx;
    cudaGetSymbolAddress(&p_rssm, g_rssm);
    cudaGetSymbolAddress(&p_a0, g_a0);
    cudaGetSymbolAddress(&p_a1, g_a1);
    cudaGetSymbolAddress(&p_dist, g_dist);
    cudaGetSymbolAddress(&p_wx, g_wx);
    cudaGetSymbolAddress(&p_bx, g_bx);
    cudaGetSymbolAddress(&p_postx, g_postx);

    const int M = B_ * T_;  // 16384

    init_state_kernel<<<64, 256>>>();
    build_wx_kernel<<<2 * S_, 256>>>(Wm, Wv, bm, bv);

    // Precompute posterior x-part (+ biases): postx = x @ Wmvx^T + bx
    gemm_f32x2_kernel<<<dim3((2 * S_) / GN, M / GM), 256>>>(
        x, (const float*)p_wx, (const float*)p_bx, (float*)p_postx,
        M, 2 * S_, I_, 0);

    scan_kernel<<<GBLK, TPB, SCAN_SMEM_BYTES>>>(W_ih, W_hh, b_ih, b_hh,
                                                Wm, Wv, noise);

    gemm_f32x2_kernel<<<dim3(H_ / GN, M / GM), 256>>>(
        (const float*)p_rssm, dW0, db0, (float*)p_a0, M, H_, R_, 1);
    gemm_f32x2_kernel<<<dim3(H_ / GN, M / GM), 256>>>(
        (const float*)p_a0, dW1, db1, (float*)p_a1, M, H_, H_, 1);
    gemm_f32x2_kernel<<<dim3(H_ / GN, M / GM), 256>>>(
        (const float*)p_a1, dW2, db2, (float*)p_a0, M, H_, H_, 1);
    gemm_f32x2_kernel<<<dim3(I_ / GN, M / GM), 256>>>(
        (const float*)p_a0, dW3, db3, (float*)p_dist, M, I_, H_, 0);

    epilogue_kernel<<<(B_ * T_ * I_ + 255) / 256, 256>>>(x, out);
}

// round 9
// speedup vs baseline: 1.2406x; 1.0561x over previous
#include <cuda_runtime.h>
#include <math.h>

// ---------------------------------------------------------------------------
// Problem dims
// ---------------------------------------------------------------------------
#define B_ 64
#define T_ 256
#define I_ 512
#define S_ 256
#define D_ 1024
#define H_ 1024
#define R_ 1280          // D_ + S_

#define GBLK 128         // persistent blocks; 1 block/SM, all co-resident
#define TPB  512         // 16 warps: 2 k-teams x 8 jl-warps
#define JPB  8           // D_/GBLK h-columns per block
#define SPB  2           // S_/GBLK z-columns per block

typedef unsigned long long ull;

// Scan shared memory layout (floats)
#define N_WHH  (24 * 1024)   // 24576
#define N_WIH  (24 * 256)    // 6144
#define N_WMVH (4 * 1024)    // 4096
#define OFF_WIH   (N_WHH)
#define OFF_WMVH  (OFF_WIH + N_WIH)          // 30720
#define OFF_STGA  (OFF_WMVH + N_WMVH)        // 34816
#define OFF_STGB  (OFF_STGA + 8192)          // 43008
#define OFF_B     (OFF_STGB + 8192)          // 51200
#define SCAN_SMEM_FLOATS (OFF_B + 64)        // 51264
#define SCAN_SMEM_BYTES  (SCAN_SMEM_FLOATS * 4)   // 205,056 B

// ---------------------------------------------------------------------------
// Device-global scratch (no runtime allocation).
// Activations (h, z) use a k-PAIRED batch-last layout:
//   element (k, b) lives at float offset (k>>1)*128 + b*2 + (k&1)
// ---------------------------------------------------------------------------
__device__ __align__(256) float g_h[D_ * B_];
__device__ __align__(256) float g_z[S_ * B_];
__device__ __align__(256) float g_wx[2 * S_ * I_];        // interleaved Wm/Wv x-part
__device__ __align__(256) float g_bx[2 * S_];
__device__ __align__(256) float g_postx[(size_t)B_ * T_ * 2 * S_];
__device__ __align__(256) float g_rssm[(size_t)B_ * T_ * R_];      // [b][t][1280]
__device__ __align__(256) float g_a0[(size_t)B_ * T_ * H_];
__device__ __align__(256) float g_a1[(size_t)B_ * T_ * H_];
__device__ __align__(256) float g_dist[(size_t)B_ * T_ * I_];

__device__ unsigned g_arrive[GBLK * 32];   // one 128B line per block
__device__ unsigned g_release;

// ---------------------------------------------------------------------------
// Packed-f32x2 helpers
// ---------------------------------------------------------------------------
__device__ __forceinline__ void ffma2(ull& d, ull a, ull b) {
    asm("fma.rn.f32x2 %0, %1, %2, %0;" : "+l"(d) : "l"(a), "l"(b));
}
__device__ __forceinline__ float sum2(ull v) {
    return __uint_as_float((unsigned)v) + __uint_as_float((unsigned)(v >> 32));
}
__device__ __forceinline__ ull packf2(float lo, float hi) {
    return (ull)__float_as_uint(lo) | ((ull)__float_as_uint(hi) << 32);
}

// ---------------------------------------------------------------------------
// Grid barrier: per-block arrival flags polled in parallel by block 0.
// ---------------------------------------------------------------------------
__device__ __forceinline__ void grid_sync(unsigned token) {
    __syncthreads();
    if (blockIdx.x == 0) {
        if (threadIdx.x > 0 && threadIdx.x < GBLK) {
            unsigned v;
            do {
                asm volatile("ld.acquire.gpu.global.u32 %0, [%1];"
                             : "=r"(v) : "l"(g_arrive + threadIdx.x * 32) : "memory");
            } while (v < token);
        }
        __syncthreads();
        if (threadIdx.x == 0) {
            asm volatile("st.release.gpu.global.u32 [%0], %1;"
                         :: "l"(&g_release), "r"(token) : "memory");
        }
    } else {
        if (threadIdx.x == 0) {
            asm volatile("st.release.gpu.global.u32 [%0], %1;"
                         :: "l"(g_arrive + blockIdx.x * 32), "r"(token) : "memory");
            unsigned v;
            do {
                asm volatile("ld.acquire.gpu.global.u32 %0, [%1];"
                             : "=r"(v) : "l"(&g_release) : "memory");
            } while (v < token);
        }
        __syncthreads();
    }
}

// Prefetch one 8192-float chunk into registers (512 threads x 4 float4).
__device__ __forceinline__ void pfetch(float4* pf, const float4* src) {
    const int t = threadIdx.x;
#pragma unroll
    for (int i = 0; i < 4; i++) pf[i] = __ldcg(src + t + i * TPB);
}
__device__ __forceinline__ void commitS(float4* dst, const float4* pf) {
    const int t = threadIdx.x;
#pragma unroll
    for (int i = 0; i < 4; i++) dst[t + i * TPB] = pf[i];
}

// ---------------------------------------------------------------------------
// One warp's half-chunk inner product: 3 GRU rows (+1 posterior row),
// 2 batches per lane, 64 k-values (the warp's team half of a 128-k chunk).
// Weight row pointers already offset by (chunk*128 + team*64).
// ---------------------------------------------------------------------------
template<bool POST>
__device__ __forceinline__ void gchunk(const float* __restrict__ stg,
        const float* __restrict__ wr, const float* __restrict__ wz,
        const float* __restrict__ wn, const float* __restrict__ wp,
        int lane, int team,
        ull& R0, ull& Z0, ull& N0, ull& R1, ull& Z1, ull& N1,
        ull& P0, ull& P1)
{
    const float* base = stg + (team * 32) * 128 + 4 * lane;
#pragma unroll
    for (int i = 0; i < 16; ++i) {
        ulonglong2 a0 = *(const ulonglong2*)(base + (2 * i) * 128);
        ulonglong2 a1 = *(const ulonglong2*)(base + (2 * i + 1) * 128);
        ulonglong2 q;
        q = *(const ulonglong2*)(wr + 4 * i);
        ffma2(R0, q.x, a0.x); ffma2(R0, q.y, a1.x);
        ffma2(R1, q.x, a0.y); ffma2(R1, q.y, a1.y);
        q = *(const ulonglong2*)(wz + 4 * i);
        ffma2(Z0, q.x, a0.x); ffma2(Z0, q.y, a1.x);
        ffma2(Z1, q.x, a0.y); ffma2(Z1, q.y, a1.y);
        q = *(const ulonglong2*)(wn + 4 * i);
        ffma2(N0, q.x, a0.x); ffma2(N0, q.y, a1.x);
        ffma2(N1, q.x, a0.y); ffma2(N1, q.y, a1.y);
        if (POST) {
            q = *(const ulonglong2*)(wp + 4 * i);
            ffma2(P0, q.x, a0.x); ffma2(P0, q.y, a1.x);
            ffma2(P1, q.x, a0.y); ffma2(P1, q.y, a1.y);
        }
    }
}

// ---------------------------------------------------------------------------
// Init: zero recurrent state + barrier state (every launch / graph replay)
// ---------------------------------------------------------------------------
__global__ void init_state_kernel() {
    const int idx = blockIdx.x * blockDim.x + threadIdx.x;
    const int stride = gridDim.x * blockDim.x;
    for (int i = idx; i < D_ * B_; i += stride) g_h[i] = 0.f;
    for (int i = idx; i < S_ * B_; i += stride) g_z[i] = 0.f;
    for (int i = idx; i < GBLK * 32; i += stride) g_arrive[i] = 0u;
    if (idx == 0) g_release = 0u;
}

// ---------------------------------------------------------------------------
// Build interleaved x-part posterior weight [2S][I] and bias (n = 2s+mv)
// ---------------------------------------------------------------------------
__global__ void build_wx_kernel(const float* __restrict__ Wm,
                                const float* __restrict__ Wv,
                                const float* __restrict__ bm,
                                const float* __restrict__ bv) {
    const int n = blockIdx.x;            // 0..511
    const int s = n >> 1, mv = n & 1;
    const float* src = (mv ? Wv : Wm) + (size_t)s * (I_ + D_);
    float* dst = g_wx + (size_t)n * I_;
    for (int k = threadIdx.x; k < I_; k += blockDim.x) dst[k] = src[k];
    if (threadIdx.x == 0) g_bx[n] = mv ? bv[s] : bm[s];
}

// ---------------------------------------------------------------------------
// Persistent scan: 512 threads = 2 k-teams x 8 jl-warps, 2 batches/lane.
// ---------------------------------------------------------------------------
__global__ void __launch_bounds__(TPB, 1) scan_kernel(
    const float* __restrict__ W_ih, const float* __restrict__ W_hh,
    const float* __restrict__ b_ih, const float* __restrict__ b_hh,
    const float* __restrict__ Wm,   const float* __restrict__ Wv,
    const float* __restrict__ noise)
{
    extern __shared__ float sm[];
    float* s_whh  = sm;
    float* s_wih  = sm + OFF_WIH;
    float* s_wmvh = sm + OFF_WMVH;
    float* s_stgA = sm + OFF_STGA;
    float* s_stgB = sm + OFF_STGB;
    float* s_bih  = sm + OFF_B;
    float* s_bhh  = sm + OFF_B + 24;

    const int tid  = threadIdx.x;
    const int lane = tid & 31;
    const int wid  = tid >> 5;        // 0..15
    const int team = wid >> 3;        // 0,1 (k-half)
    const int wj   = wid & 7;         // jl index 0..7
    const int bid  = blockIdx.x;
    const int j0g  = bid * JPB;
    const int s0g  = bid * SPB;
    const bool has_post = (wj < 4);
    const int prow = wj & 3;          // posterior row = 2*sl + mv

    // ---- weight slices into smem ----
    for (int v = tid; v < 24 * 256; v += TPB) {
        int row = v >> 8, c = v & 255;
        int jl = row / 3, g = row % 3;
        ((float4*)s_whh)[v] = ((const float4*)(W_hh + (size_t)(g * D_ + j0g + jl) * D_))[c];
    }
    for (int v = tid; v < 24 * 64; v += TPB) {
        int row = v >> 6, c = v & 63;
        int jl = row / 3, g = row % 3;
        ((float4*)s_wih)[v] = ((const float4*)(W_ih + (size_t)(g * D_ + j0g + jl) * S_))[c];
    }
    for (int v = tid; v < 4 * 256; v += TPB) {
        int row = v >> 8, c = v & 255;
        int sl = row >> 1, mv = row & 1;
        const float* W = (mv ? Wv : Wm) + (size_t)(s0g + sl) * (I_ + D_) + I_;
        ((float4*)s_wmvh)[v] = ((const float4*)W)[c];
    }
    if (tid < 24) {
        int jl = tid / 3, g = tid % 3;
        s_bih[tid] = b_ih[g * D_ + j0g + jl];
        s_bhh[tid] = b_hh[g * D_ + j0g + jl];
    }
    __syncthreads();

    // per-warp row pointers
    const float* wihR = s_wih + (wj * 3 + 0) * S_;
    const float* wihZ = s_wih + (wj * 3 + 1) * S_;
    const float* wihN = s_wih + (wj * 3 + 2) * S_;
    const float* whhR = s_whh + (wj * 3 + 0) * D_;
    const float* whhZ = s_whh + (wj * 3 + 1) * D_;
    const float* whhN = s_whh + (wj * 3 + 2) * D_;
    const float* wpR  = s_wmvh + prow * D_;

    const float4* z4 = (const float4*)g_z;
    const float4* h4 = (const float4*)g_h;

    float4 pf[4];
    // carried accumulators: R/Z hold (gh r/z for next step, later + gi r/z);
    // ghn holds gh n-gate. Team-half partials.
    ull R0 = 0, Z0 = 0, R1 = 0, Z1 = 0, ghn0 = 0, ghn1 = 0;
    float hp0 = 0.f, hp1 = 0.f;      // h_prev, team A only
    ull du0, du1;                    // dummies for POST=false

    pfetch(pf, z4);                  // z_{-1} = zeros

    for (int t = 0; t < T_; ++t) {
        float2 px = make_float2(0.f, 0.f);
        float nz = 0.f;
        if (tid < 128) {
            int slq = tid >> 6, bq = tid & 63;
            px = __ldcg((const float2*)(g_postx +
                    ((size_t)bq * T_ + t) * (2 * S_) + 2 * (s0g + slq)));
            nz = __ldcg(noise + ((size_t)t * B_ + bq) * S_ + s0g + slq);
        }

        // ========== (A) gi over z_{t-1}: 2 chunks, r/z into R/Z ==========
        ull gin0 = 0, gin1 = 0;
        {
            commitS((float4*)s_stgA, pf); __syncthreads();
            pfetch(pf, z4 + 2048);
            int off = 0 * 128 + team * 64;
            gchunk<false>(s_stgA, wihR + off, wihZ + off, wihN + off, 0,
                          lane, team, R0, Z0, gin0, R1, Z1, gin1, du0, du1);
            commitS((float4*)s_stgB, pf); __syncthreads();
            off = 1 * 128 + team * 64;
            gchunk<false>(s_stgB, wihR + off, wihZ + off, wihN + off, 0,
                          lane, team, R0, Z0, gin0, R1, Z1, gin1, du0, du1);
        }

        // ---- finalize h_t: cross-team reduce through stgA ----
        {
            ull* red = (ull*)s_stgA;
            if (team == 1) {
                ull* r = red + (size_t)(wj * 32 + lane) * 8;
                r[0] = R0; r[1] = Z0; r[2] = gin0; r[3] = ghn0;
                r[4] = R1; r[5] = Z1; r[6] = gin1; r[7] = ghn1;
            }
            __syncthreads();
            if (team == 0) {
                const ull* r = red + (size_t)(wj * 32 + lane) * 8;
                float br = s_bih[wj * 3 + 0] + s_bhh[wj * 3 + 0];
                float bz = s_bih[wj * 3 + 1] + s_bhh[wj * 3 + 1];
                float bin = s_bih[wj * 3 + 2];
                float bhn = s_bhh[wj * 3 + 2];
                float vr0 = sum2(R0) + sum2(r[0]) + br;
                float vz0 = sum2(Z0) + sum2(r[1]) + bz;
                float gi0 = sum2(gin0) + sum2(r[2]) + bin;
                float gh0 = sum2(ghn0) + sum2(r[3]) + bhn;
                float vr1 = sum2(R1) + sum2(r[4]) + br;
                float vz1 = sum2(Z1) + sum2(r[5]) + bz;
                float gi1 = sum2(gin1) + sum2(r[6]) + bin;
                float gh1 = sum2(ghn1) + sum2(r[7]) + bhn;

                float rr0 = 1.f / (1.f + expf(-vr0));
                float zg0 = 1.f / (1.f + expf(-vz0));
                float nn0 = tanhf(gi0 + rr0 * gh0);
                float hn0 = (1.f - zg0) * nn0 + zg0 * hp0;
                float rr1 = 1.f / (1.f + expf(-vr1));
                float zg1 = 1.f / (1.f + expf(-vz1));
                float nn1 = tanhf(gi1 + rr1 * gh1);
                float hn1 = (1.f - zg1) * nn1 + zg1 * hp1;
                hp0 = hn0; hp1 = hn1;

                int j = j0g + wj;
                size_t hoff = (size_t)(j >> 1) * 128 + (j & 1);
                __stcg(&g_h[hoff + 4 * lane], hn0);
                __stcg(&g_h[hoff + 4 * lane + 2], hn1);
                g_rssm[((size_t)(2 * lane) * T_ + t) * R_ + j] = hn0;
                g_rssm[((size_t)(2 * lane + 1) * T_ + t) * R_ + j] = hn1;
            }
            // reset carried accumulators for gh_{t+1}
            R0 = 0; Z0 = 0; R1 = 0; Z1 = 0; ghn0 = 0; ghn1 = 0;
        }

        grid_sync(2 * t + 1);     // h_t visible everywhere
        pfetch(pf, h4);           // exposed latency (unavoidable after sync)

        // ==== (B) h-pass over h_t: gh_{t+1} + posterior h-part, 8 chunks ====
        ull P0 = 0, P1 = 0;
        for (int c = 0; c < 8; ++c) {
            float* buf = (c & 1) ? s_stgB : s_stgA;
            commitS((float4*)buf, pf); __syncthreads();
            if (c < 7) pfetch(pf, h4 + (c + 1) * 2048);
            int off = c * 128 + team * 64;
            if (has_post)
                gchunk<true>(buf, whhR + off, whhZ + off, whhN + off, wpR + off,
                             lane, team, R0, Z0, ghn0, R1, Z1, ghn1, P0, P1);
            else
                gchunk<false>(buf, whhR + off, whhZ + off, whhN + off, 0,
                              lane, team, R0, Z0, ghn0, R1, Z1, ghn1, du0, du1);
        }

        // ---- finalize z_t: posterior reduce through stgA ----
        {
            ull* red2 = (ull*)s_stgA;
            if (has_post) {
                red2[(size_t)((team * 4 + prow) * 64 + 2 * lane)] = P0;
                red2[(size_t)((team * 4 + prow) * 64 + 2 * lane + 1)] = P1;
            }
            __syncthreads();
            if (tid < 128) {
                int sl = tid >> 6, b = tid & 63;
                float m = sum2(red2[(2 * sl) * 64 + b]) +
                          sum2(red2[(4 + 2 * sl) * 64 + b]) + px.x;
                float v = sum2(red2[(2 * sl + 1) * 64 + b]) +
                          sum2(red2[(4 + 2 * sl + 1) * 64 + b]) + px.y;
                float zv = nz * expf(0.5f * v) + m;
                int sg = s0g + sl;
                __stcg(&g_z[(size_t)(sg >> 1) * 128 + b * 2 + (sg & 1)], zv);
                g_rssm[((size_t)b * T_ + t) * R_ + D_ + sg] = zv;
            }
        }

        grid_sync(2 * t + 2);     // z_t visible everywhere
        pfetch(pf, z4);           // next step's first chunk
    }
}

// ---------------------------------------------------------------------------
// Decoder GEMM, packed-f32x2, GK=32, double-buffered smem.
// ---------------------------------------------------------------------------
#define GM 128
#define GN 64
#define GK 32
#define KK2 (GK / 2)

__global__ void __launch_bounds__(256, 2) gemm_f32x2_kernel(
    const float* __restrict__ A, const float* __restrict__ W,
    const float* __restrict__ bias, float* __restrict__ C,
    int M, int N, int K, int act)
{
    __shared__ ull As2[2][KK2][GM];
    __shared__ ull Ws2[2][KK2][GN];
    const int tid = threadIdx.x;
    const int bm = blockIdx.y * GM;
    const int bn = blockIdx.x * GN;
    const int tx = tid & 15, ty = tid >> 4;
    const int m0 = ty * 8, n0 = tx * 4;

    const int part = tid & 7;
    const int lrow = tid >> 3;

    ull acc[8][4];
#pragma unroll
    for (int i = 0; i < 8; ++i)
#pragma unroll
        for (int j = 0; j < 4; ++j) acc[i][j] = 0ULL;

    float4 va[4], vw[2];
#pragma unroll
    for (int i = 0; i < 4; ++i)
        va[i] = *(const float4*)(A + (size_t)(bm + lrow + i * 32) * K + part * 4);
#pragma unroll
    for (int i = 0; i < 2; ++i)
        vw[i] = *(const float4*)(W + (size_t)(bn + lrow + i * 32) * K + part * 4);

#pragma unroll
    for (int i = 0; i < 4; ++i) {
        As2[0][part * 2 + 0][lrow + i * 32] = packf2(va[i].x, va[i].y);
        As2[0][part * 2 + 1][lrow + i * 32] = packf2(va[i].z, va[i].w);
    }
#pragma unroll
    for (int i = 0; i < 2; ++i) {
        Ws2[0][part * 2 + 0][lrow + i * 32] = packf2(vw[i].x, vw[i].y);
        Ws2[0][part * 2 + 1][lrow + i * 32] = packf2(vw[i].z, vw[i].w);
    }

    const int niter = K / GK;
    int buf = 0;
    for (int kb = 0; kb < niter; ++kb) {
        __syncthreads();
        if (kb + 1 < niter) {
            int ko = (kb + 1) * GK + part * 4;
#pragma unroll
            for (int i = 0; i < 4; ++i)
                va[i] = *(const float4*)(A + (size_t)(bm + lrow + i * 32) * K + ko);
#pragma unroll
            for (int i = 0; i < 2; ++i)
                vw[i] = *(const float4*)(W + (size_t)(bn + lrow + i * 32) * K + ko);
        }
#pragma unroll
        for (int k2 = 0; k2 < KK2; ++k2) {
            ull ra[8], rw[4];
            *(ulonglong2*)&ra[0] = *(const ulonglong2*)&As2[buf][k2][m0 + 0];
            *(ulonglong2*)&ra[2] = *(const ulonglong2*)&As2[buf][k2][m0 + 2];
            *(ulonglong2*)&ra[4] = *(const ulonglong2*)&As2[buf][k2][m0 + 4];
            *(ulonglong2*)&ra[6] = *(const ulonglong2*)&As2[buf][k2][m0 + 6];
            *(ulonglong2*)&rw[0] = *(const ulonglong2*)&Ws2[buf][k2][n0 + 0];
            *(ulonglong2*)&rw[2] = *(const ulonglong2*)&Ws2[buf][k2][n0 + 2];
#pragma unroll
            for (int i = 0; i < 8; ++i)
#pragma unroll
                for (int j = 0; j < 4; ++j) ffma2(acc[i][j], ra[i], rw[j]);
        }
        if (kb + 1 < niter) {
            int nb = buf ^ 1;
#pragma unroll
            for (int i = 0; i < 4; ++i) {
                As2[nb][part * 2 + 0][lrow + i * 32] = packf2(va[i].x, va[i].y);
                As2[nb][part * 2 + 1][lrow + i * 32] = packf2(va[i].z, va[i].w);
            }
#pragma unroll
            for (int i = 0; i < 2; ++i) {
                Ws2[nb][part * 2 + 0][lrow + i * 32] = packf2(vw[i].x, vw[i].y);
                Ws2[nb][part * 2 + 1][lrow + i * 32] = packf2(vw[i].z, vw[i].w);
            }
            buf = nb;
        }
    }

    float bb[4];
#pragma unroll
    for (int j = 0; j < 4; ++j) bb[j] = bias[bn + n0 + j];
#pragma unroll
    for (int i = 0; i < 8; ++i) {
        float r[4];
#pragma unroll
        for (int j = 0; j < 4; ++j) {
            float v = sum2(acc[i][j]) + bb[j];
            r[j] = act ? (v > 0.f ? v : expm1f(v)) : v;
        }
        *(float4*)(C + (size_t)(bm + m0 + i) * N + bn + n0) =
            make_float4(r[0], r[1], r[2], r[3]);
    }
}

// ---------------------------------------------------------------------------
// Epilogue: build (x_delta_hat, x_hat) into d_out
// ---------------------------------------------------------------------------
__global__ void epilogue_kernel(const float* __restrict__ x, float* __restrict__ out) {
    size_t idx = (size_t)blockIdx.x * blockDim.x + threadIdx.x;
    const size_t total = (size_t)B_ * T_ * I_;
    if (idx >= total) return;
    int i = (int)(idx & (I_ - 1));
    size_t bt = idx >> 9;
    int t = (int)(bt & (T_ - 1));
    int b = (int)(bt >> 8);

    float xh;
    if (t == 0) xh = x[idx];
    else        xh = x[idx - I_] + g_dist[idx - I_];
    out[(size_t)B_ * (T_ - 1) * I_ + idx] = xh;

    if (t < T_ - 1)
        out[((size_t)b * (T_ - 1) + t) * I_ + i] = g_dist[idx];
}

// ---------------------------------------------------------------------------
// kernel_launch
// ---------------------------------------------------------------------------
extern "C" void kernel_launch(void* const* d_in, const int* in_sizes, int n_in,
                              void* d_out, int out_size) {
    const float* x     = (const float*)d_in[0];
    const float* noise = (const float*)d_in[1];
    const float* W_ih  = (const float*)d_in[2];
    const float* W_hh  = (const float*)d_in[3];
    const float* b_ih  = (const float*)d_in[4];
    const float* b_hh  = (const float*)d_in[5];
    const float* Wm    = (const float*)d_in[6];
    const float* bm    = (const float*)d_in[7];
    const float* Wv    = (const float*)d_in[8];
    const float* bv    = (const float*)d_in[9];
    const float* dW0   = (const float*)d_in[10];
    const float* db0   = (const float*)d_in[11];
    const float* dW1   = (const float*)d_in[12];
    const float* db1   = (const float*)d_in[13];
    const float* dW2   = (const float*)d_in[14];
    const float* db2   = (const float*)d_in[15];
    const float* dW3   = (const float*)d_in[16];
    const float* db3   = (const float*)d_in[17];
    float* out = (float*)d_out;

    cudaFuncSetAttribute(scan_kernel, cudaFuncAttributeMaxDynamicSharedMemorySize,
                         SCAN_SMEM_BYTES);

    void *p_rssm, *p_a0, *p_a1, *p_dist, *p_wx, *p_bx, *p_postx;
    cudaGetSymbolAddress(&p_rssm, g_rssm);
    cudaGetSymbolAddress(&p_a0, g_a0);
    cudaGetSymbolAddress(&p_a1, g_a1);
    cudaGetSymbolAddress(&p_dist, g_dist);
    cudaGetSymbolAddress(&p_wx, g_wx);
    cudaGetSymbolAddress(&p_bx, g_bx);
    cudaGetSymbolAddress(&p_postx, g_postx);

    const int M = B_ * T_;  // 16384

    init_state_kernel<<<64, 256>>>();
    build_wx_kernel<<<2 * S_, 256>>>(Wm, Wv, bm, bv);

    // Precompute posterior x-part (+ biases): postx = x @ Wmvx^T + bx
    gemm_f32x2_kernel<<<dim3((2 * S_) / GN, M / GM), 256>>>(
        x, (const float*)p_wx, (const float*)p_bx, (float*)p_postx,
        M, 2 * S_, I_, 0);

    scan_kernel<<<GBLK, TPB, SCAN_SMEM_BYTES>>>(W_ih, W_hh, b_ih, b_hh,
                                                Wm, Wv, noise);

    gemm_f32x2_kernel<<<dim3(H_ / GN, M / GM), 256>>>(
        (const float*)p_rssm, dW0, db0, (float*)p_a0, M, H_, R_, 1);
    gemm_f32x2_kernel<<<dim3(H_ / GN, M / GM), 256>>>(
        (const float*)p_a0, dW1, db1, (float*)p_a1, M, H_, H_, 1);
    gemm_f32x2_kernel<<<dim3(H_ / GN, M / GM), 256>>>(
        (const float*)p_a1, dW2, db2, (float*)p_a0, M, H_, H_, 1);
    gemm_f32x2_kernel<<<dim3(I_ / GN, M / GM), 256>>>(
        (const float*)p_a0, dW3, db3, (float*)p_dist, M, I_, H_, 0);

    epilogue_kernel<<<(B_ * T_ * I_ + 255) / 256, 256>>>(x, out);
}